// round 1
// baseline (speedup 1.0000x reference)
#include <cuda_runtime.h>
#include <mma.h>

using namespace nvcuda;

// Problem constants
#define B_IMG   64
#define N_OBJ   64
#define E_EDGE  512
#define M_EDGE  (B_IMG * E_EDGE)     // 32768
#define OBJDIM  2048
#define QDIM    1024
#define KS      8
#define HID     512
#define HIDKS   (HID * KS)           // 4096

// Scratch (no cudaMalloc allowed): 8 MB + 1 MB + 2 KB
__device__ float g_node_h[(size_t)B_IMG * N_OBJ * HID];   // [4096, 512]
__device__ float g_q_h[(size_t)B_IMG * HIDKS];            // [64, 4096]
__device__ float g_inv_norm[B_IMG * KS];                  // [64, 8]

// ---------------------------------------------------------------------------
// TF32 tensor-core GEMM with fused bias + ReLU.
// C[M,N] = relu(A[M,K] @ B[K,N] + bias[N]).  A, B row-major fp32 in global;
// values are rounded to tf32 once while staging to shared memory.
// Warp tile 32x32 (2x2 wmma 16x16x8 frags). Requires M%BM==0, N%BN==0, K%BK==0.
// ---------------------------------------------------------------------------
template<int BM, int BN, int BK, int NWARPS>
__global__ __launch_bounds__(NWARPS * 32)
void gemm_bias_relu(const float* __restrict__ A, const float* __restrict__ Bm,
                    const float* __restrict__ bias, float* __restrict__ C,
                    int Kdim, int Ndim)
{
    static_assert(NWARPS == (BM / 32) * (BN / 32), "warp tiling mismatch");
    constexpr int NT = NWARPS * 32;
    constexpr int AP = BK + 4;            // padded lda for smem A (stays 16B aligned)
    constexpr int BP = BN + 4;            // padded ldb for smem B / C
    constexpr int WROWS = BM / 32;
    constexpr int SMEM_AB = BM * AP + BK * BP;
    constexpr int SMEM_C  = BM * BP;
    constexpr int SMEM = (SMEM_AB > SMEM_C) ? SMEM_AB : SMEM_C;
    __shared__ __align__(16) float smem[SMEM];
    float* As = smem;
    float* Bs = smem + BM * AP;
    float* Cs = smem;                     // reused for epilogue

    const int tid    = threadIdx.x;
    const int warpId = tid >> 5;
    const int wm     = warpId % WROWS;    // warp row within block tile
    const int wn     = warpId / WROWS;    // warp col within block tile
    const int blockM = blockIdx.y * BM;
    const int blockN = blockIdx.x * BN;

    wmma::fragment<wmma::accumulator, 16, 16, 8, float> acc[2][2];
#pragma unroll
    for (int i = 0; i < 2; i++)
#pragma unroll
        for (int j = 0; j < 2; j++)
            wmma::fill_fragment(acc[i][j], 0.0f);

    for (int k0 = 0; k0 < Kdim; k0 += BK) {
        // Stage A tile (BM x BK), tf32-round on the way in
#pragma unroll
        for (int i = 0; i < (BM * BK / 4) / NT; i++) {
            int l = tid + i * NT;
            int r = l / (BK / 4);
            int c = l % (BK / 4);
            float4 v = __ldg((const float4*)(A + (size_t)(blockM + r) * Kdim + k0 + c * 4));
            v.x = wmma::__float_to_tf32(v.x);
            v.y = wmma::__float_to_tf32(v.y);
            v.z = wmma::__float_to_tf32(v.z);
            v.w = wmma::__float_to_tf32(v.w);
            *(float4*)(As + r * AP + c * 4) = v;
        }
        // Stage B tile (BK x BN)
#pragma unroll
        for (int i = 0; i < (BK * BN / 4) / NT; i++) {
            int l = tid + i * NT;
            int r = l / (BN / 4);
            int c = l % (BN / 4);
            float4 v = __ldg((const float4*)(Bm + (size_t)(k0 + r) * Ndim + blockN + c * 4));
            v.x = wmma::__float_to_tf32(v.x);
            v.y = wmma::__float_to_tf32(v.y);
            v.z = wmma::__float_to_tf32(v.z);
            v.w = wmma::__float_to_tf32(v.w);
            *(float4*)(Bs + r * BP + c * 4) = v;
        }
        __syncthreads();

#pragma unroll
        for (int kk = 0; kk < BK; kk += 8) {
            wmma::fragment<wmma::matrix_a, 16, 16, 8, wmma::precision::tf32, wmma::row_major> af[2];
            wmma::fragment<wmma::matrix_b, 16, 16, 8, wmma::precision::tf32, wmma::row_major> bf[2];
#pragma unroll
            for (int i = 0; i < 2; i++)
                wmma::load_matrix_sync(af[i], As + (wm * 32 + i * 16) * AP + kk, AP);
#pragma unroll
            for (int j = 0; j < 2; j++)
                wmma::load_matrix_sync(bf[j], Bs + kk * BP + wn * 32 + j * 16, BP);
#pragma unroll
            for (int i = 0; i < 2; i++)
#pragma unroll
                for (int j = 0; j < 2; j++)
                    wmma::mma_sync(acc[i][j], af[i], bf[j], acc[i][j]);
        }
        __syncthreads();
    }

    // Epilogue: dump accumulators to smem, then fused bias+ReLU vectorized store
#pragma unroll
    for (int i = 0; i < 2; i++)
#pragma unroll
        for (int j = 0; j < 2; j++)
            wmma::store_matrix_sync(Cs + (wm * 32 + i * 16) * BP + wn * 32 + j * 16,
                                    acc[i][j], BP, wmma::mem_row_major);
    __syncthreads();
#pragma unroll
    for (int i = 0; i < (BM * BN / 4) / NT; i++) {
        int l = tid + i * NT;
        int r = l / (BN / 4);
        int c = l % (BN / 4);
        float4 v  = *(float4*)(Cs + r * BP + c * 4);
        float4 bb = __ldg((const float4*)(bias + blockN + c * 4));
        v.x = fmaxf(v.x + bb.x, 0.0f);
        v.y = fmaxf(v.y + bb.y, 0.0f);
        v.z = fmaxf(v.z + bb.z, 0.0f);
        v.w = fmaxf(v.w + bb.w, 0.0f);
        *(float4*)(C + (size_t)(blockM + r) * Ndim + blockN + c * 4) = v;
    }
}

// ---------------------------------------------------------------------------
// Per-(batch, k) inverse norm of q_e: inv[b,k] = 1/sqrt(sum_h q_h[b, h*KS+k]^2)
// One block per batch image.
// ---------------------------------------------------------------------------
__global__ __launch_bounds__(256)
void qnorm_kernel(const float* __restrict__ qh, float* __restrict__ inv)
{
    const int b   = blockIdx.x;
    const int tid = threadIdx.x;
    const float* q = qh + (size_t)b * HIDKS;

    float acc[KS];
#pragma unroll
    for (int k = 0; k < KS; k++) acc[k] = 0.0f;

    for (int h = tid; h < HID; h += 256) {
        float4 q0 = *(const float4*)(q + h * KS);
        float4 q1 = *(const float4*)(q + h * KS + 4);
        acc[0] += q0.x * q0.x; acc[1] += q0.y * q0.y;
        acc[2] += q0.z * q0.z; acc[3] += q0.w * q0.w;
        acc[4] += q1.x * q1.x; acc[5] += q1.y * q1.y;
        acc[6] += q1.z * q1.z; acc[7] += q1.w * q1.w;
    }

    __shared__ float red[KS * 256];
#pragma unroll
    for (int k = 0; k < KS; k++) red[k * 256 + tid] = acc[k];
    __syncthreads();
    for (int s = 128; s > 0; s >>= 1) {
        if (tid < s) {
#pragma unroll
            for (int k = 0; k < KS; k++)
                red[k * 256 + tid] += red[k * 256 + tid + s];
        }
        __syncthreads();
    }
    if (tid < KS)
        inv[b * KS + tid] = 1.0f / sqrtf(red[tid * 256]);
}

// ---------------------------------------------------------------------------
// Edge kernel: one warp per edge.
// out[m,k] = inv[b,k] * sum_h (node_h[b,src,h] + node_h[b,dst,h]) * q_h[b, h*KS+k]
// node rows (2KB each) and the 16KB q row are L1-resident per batch.
// ---------------------------------------------------------------------------
__global__ __launch_bounds__(256)
void edge_kernel(const int* __restrict__ indexes,
                 const float* __restrict__ nh,
                 const float* __restrict__ qh,
                 const float* __restrict__ inv,
                 float* __restrict__ out)
{
    const int warp = (blockIdx.x * blockDim.x + threadIdx.x) >> 5;
    const int lane = threadIdx.x & 31;
    if (warp >= M_EDGE) return;

    const int idx = __ldg(indexes + warp);
    const int b   = idx >> 12;          // / (N*N) = 4096
    const int rem = idx & 4095;
    const int src = rem >> 6;           // / N
    const int dst = rem & 63;           // % N

    const float* rs = nh + (size_t)(b * N_OBJ + src) * HID;
    const float* rd = nh + (size_t)(b * N_OBJ + dst) * HID;
    const float* q  = qh + (size_t)b * HIDKS;

    float acc[KS];
#pragma unroll
    for (int k = 0; k < KS; k++) acc[k] = 0.0f;

#pragma unroll 4
    for (int h = lane; h < HID; h += 32) {
        float o = __ldg(rs + h) + __ldg(rd + h);
        float4 q0 = __ldg((const float4*)(q + h * KS));
        float4 q1 = __ldg((const float4*)(q + h * KS) + 1);
        acc[0] += o * q0.x; acc[1] += o * q0.y;
        acc[2] += o * q0.z; acc[3] += o * q0.w;
        acc[4] += o * q1.x; acc[5] += o * q1.y;
        acc[6] += o * q1.z; acc[7] += o * q1.w;
    }

#pragma unroll
    for (int k = 0; k < KS; k++) {
        acc[k] += __shfl_xor_sync(0xFFFFFFFFu, acc[k], 16);
        acc[k] += __shfl_xor_sync(0xFFFFFFFFu, acc[k], 8);
        acc[k] += __shfl_xor_sync(0xFFFFFFFFu, acc[k], 4);
        acc[k] += __shfl_xor_sync(0xFFFFFFFFu, acc[k], 2);
        acc[k] += __shfl_xor_sync(0xFFFFFFFFu, acc[k], 1);
    }

    if (lane == 0) {
        float4 i0 = *(const float4*)(inv + b * KS);
        float4 i1 = *(const float4*)(inv + b * KS + 4);
        float4 o0 = make_float4(acc[0] * i0.x, acc[1] * i0.y, acc[2] * i0.z, acc[3] * i0.w);
        float4 o1 = make_float4(acc[4] * i1.x, acc[5] * i1.y, acc[6] * i1.z, acc[7] * i1.w);
        ((float4*)out)[(size_t)warp * 2]     = o0;
        ((float4*)out)[(size_t)warp * 2 + 1] = o1;
    }
}

// ---------------------------------------------------------------------------
extern "C" void kernel_launch(void* const* d_in, const int* in_sizes, int n_in,
                              void* d_out, int out_size)
{
    const float* node_feats = (const float*)d_in[0];   // [64,64,2048]
    const float* q_feats    = (const float*)d_in[1];   // [64,1024]
    const int*   indexes    = (const int*)d_in[2];     // [32768]
    const float* W_obj      = (const float*)d_in[3];   // [2048,512]
    const float* b_obj      = (const float*)d_in[4];   // [512]
    const float* W_q        = (const float*)d_in[5];   // [1024,4096]
    const float* b_q        = (const float*)d_in[6];   // [4096]
    float* out = (float*)d_out;                        // [32768,8]

    float *nh, *qh, *inv;
    cudaGetSymbolAddress((void**)&nh,  g_node_h);
    cudaGetSymbolAddress((void**)&qh,  g_q_h);
    cudaGetSymbolAddress((void**)&inv, g_inv_norm);

    // GEMM1: node_h[4096,512] = relu(node_feats @ W_obj + b_obj)
    gemm_bias_relu<128, 64, 32, 8>
        <<<dim3(HID / 64, (B_IMG * N_OBJ) / 128), 256>>>(node_feats, W_obj, b_obj, nh,
                                                         OBJDIM, HID);
    // GEMM2: q_h[64,4096] = relu(q_feats @ W_q + b_q)
    gemm_bias_relu<64, 64, 32, 4>
        <<<dim3(HIDKS / 64, B_IMG / 64), 128>>>(q_feats, W_q, b_q, qh,
                                                QDIM, HIDKS);
    // Per-(batch,k) inverse norms
    qnorm_kernel<<<B_IMG, 256>>>(qh, inv);
    // Edge gather + dot + scale
    edge_kernel<<<M_EDGE / 8, 256>>>(indexes, nh, qh, inv, out);
}

// round 2
// speedup vs baseline: 1.0315x; 1.0315x over previous
#include <cuda_runtime.h>
#include <mma.h>

using namespace nvcuda;

// Problem constants
#define B_IMG   64
#define N_OBJ   64
#define E_EDGE  512
#define M_EDGE  (B_IMG * E_EDGE)     // 32768
#define OBJDIM  2048
#define QDIM    1024
#define KS      8
#define HID     512
#define HIDKS   (HID * KS)           // 4096

// Scratch (no cudaMalloc allowed)
__device__ float g_node_h[(size_t)B_IMG * N_OBJ * HID];   // [4096, 512]
__device__ float g_q_h[(size_t)B_IMG * HIDKS];            // [64, 4096]
__device__ float g_inv_norm[B_IMG * KS];                  // [64, 8]

// ---------------------------------------------------------------------------
// cp.async helpers
// ---------------------------------------------------------------------------
__device__ __forceinline__ void cp_async16(float* dst_smem, const float* src_gmem) {
    unsigned d = (unsigned)__cvta_generic_to_shared(dst_smem);
    asm volatile("cp.async.cg.shared.global [%0], [%1], 16;\n" :: "r"(d), "l"(src_gmem));
}
__device__ __forceinline__ void cp_commit() {
    asm volatile("cp.async.commit_group;\n");
}
template<int N>
__device__ __forceinline__ void cp_wait() {
    asm volatile("cp.async.wait_group %0;\n" :: "n"(N));
}

// ---------------------------------------------------------------------------
// TF32 tensor-core GEMM, cp.async double-buffered, fused bias + ReLU.
// C[M,N] = relu(A[M,K] @ B[K,N] + bias[N]).  A, B row-major fp32.
// Block tile BM x BN, K-slab BK=32, WM x WN warps, warp tile
// (BM/WM) x (BN/WN) of 16x16x8 tf32 wmma fragments.
// ---------------------------------------------------------------------------
template<int BM, int BN, int BK, int WM, int WN>
__global__ __launch_bounds__(WM * WN * 32)
void gemm_tf32_pipe(const float* __restrict__ A, const float* __restrict__ Bm,
                    const float* __restrict__ bias, float* __restrict__ C,
                    int Kdim, int Ndim)
{
    constexpr int NWARPS = WM * WN;
    constexpr int NT = NWARPS * 32;
    constexpr int FM = BM / WM / 16;       // a-frags per warp (M)
    constexpr int FN = BN / WN / 16;       // b-frags per warp (N)
    constexpr int AP = BK + 4;             // padded smem lda (keeps 16B align: AP%4==0)
    constexpr int BP = BN + 4;
    constexpr int A_ITERS = (BM * BK / 4) / NT;
    constexpr int B_ITERS = (BK * BN / 4) / NT;
    static_assert(A_ITERS * NT * 4 == BM * BK, "A tile split");
    static_assert(B_ITERS * NT * 4 == BK * BN, "B tile split");

    extern __shared__ __align__(16) float smem[];
    float* As = smem;                       // 2 stages of BM x AP
    float* Bs = smem + 2 * BM * AP;         // 2 stages of BK x BP
    float* Cs = smem;                       // epilogue reuse

    const int tid    = threadIdx.x;
    const int warpId = tid >> 5;
    const int wm     = warpId % WM;
    const int wn     = warpId / WM;
    const int blockM = blockIdx.y * BM;
    const int blockN = blockIdx.x * BN;

    auto load_stage = [&](int s, int k0) {
#pragma unroll
        for (int i = 0; i < A_ITERS; i++) {
            int l = tid + i * NT;
            int r = l / (BK / 4);
            int c = l % (BK / 4);
            cp_async16(As + s * BM * AP + r * AP + c * 4,
                       A + (size_t)(blockM + r) * Kdim + k0 + c * 4);
        }
#pragma unroll
        for (int i = 0; i < B_ITERS; i++) {
            int l = tid + i * NT;
            int r = l / (BN / 4);
            int c = l % (BN / 4);
            cp_async16(Bs + s * BK * BP + r * BP + c * 4,
                       Bm + (size_t)(k0 + r) * Ndim + blockN + c * 4);
        }
    };

    wmma::fragment<wmma::accumulator, 16, 16, 8, float> acc[FM][FN];
#pragma unroll
    for (int i = 0; i < FM; i++)
#pragma unroll
        for (int j = 0; j < FN; j++)
            wmma::fill_fragment(acc[i][j], 0.0f);

    const int NIT = Kdim / BK;
    load_stage(0, 0);
    cp_commit();

    for (int it = 0; it < NIT; ++it) {
        if (it + 1 < NIT) {
            load_stage((it + 1) & 1, (it + 1) * BK);
            cp_commit();
            cp_wait<1>();
        } else {
            cp_wait<0>();
        }
        __syncthreads();

        const float* as = As + (it & 1) * BM * AP;
        const float* bs = Bs + (it & 1) * BK * BP;
#pragma unroll
        for (int kk = 0; kk < BK; kk += 8) {
            wmma::fragment<wmma::matrix_a, 16, 16, 8, wmma::precision::tf32, wmma::row_major> af[FM];
            wmma::fragment<wmma::matrix_b, 16, 16, 8, wmma::precision::tf32, wmma::row_major> bf[FN];
#pragma unroll
            for (int i = 0; i < FM; i++) {
                wmma::load_matrix_sync(af[i], as + (wm * FM * 16 + i * 16) * AP + kk, AP);
#pragma unroll
                for (int t = 0; t < af[i].num_elements; t++)
                    af[i].x[t] = wmma::__float_to_tf32(af[i].x[t]);
            }
#pragma unroll
            for (int j = 0; j < FN; j++) {
                wmma::load_matrix_sync(bf[j], bs + kk * BP + wn * FN * 16 + j * 16, BP);
#pragma unroll
                for (int t = 0; t < bf[j].num_elements; t++)
                    bf[j].x[t] = wmma::__float_to_tf32(bf[j].x[t]);
            }
#pragma unroll
            for (int i = 0; i < FM; i++)
#pragma unroll
                for (int j = 0; j < FN; j++)
                    wmma::mma_sync(acc[i][j], af[i], bf[j], acc[i][j]);
        }
        __syncthreads();   // all warps done with this stage before it is overwritten
    }

    // Epilogue: accumulators -> smem -> fused bias+ReLU vectorized store
#pragma unroll
    for (int i = 0; i < FM; i++)
#pragma unroll
        for (int j = 0; j < FN; j++)
            wmma::store_matrix_sync(Cs + (wm * FM * 16 + i * 16) * BP + wn * FN * 16 + j * 16,
                                    acc[i][j], BP, wmma::mem_row_major);
    __syncthreads();
#pragma unroll
    for (int i = 0; i < (BM * BN / 4) / NT; i++) {
        int l = tid + i * NT;
        int r = l / (BN / 4);
        int c = l % (BN / 4);
        float4 v  = *(float4*)(Cs + r * BP + c * 4);
        float4 bb = __ldg((const float4*)(bias + blockN + c * 4));
        v.x = fmaxf(v.x + bb.x, 0.0f);
        v.y = fmaxf(v.y + bb.y, 0.0f);
        v.z = fmaxf(v.z + bb.z, 0.0f);
        v.w = fmaxf(v.w + bb.w, 0.0f);
        *(float4*)(C + (size_t)(blockM + r) * Ndim + blockN + c * 4) = v;
    }
}

// ---------------------------------------------------------------------------
// Per-(batch, k) inverse norm of q_e
// ---------------------------------------------------------------------------
__global__ __launch_bounds__(256)
void qnorm_kernel(const float* __restrict__ qh, float* __restrict__ inv)
{
    const int b   = blockIdx.x;
    const int tid = threadIdx.x;
    const float* q = qh + (size_t)b * HIDKS;

    float acc[KS];
#pragma unroll
    for (int k = 0; k < KS; k++) acc[k] = 0.0f;

    for (int h = tid; h < HID; h += 256) {
        float4 q0 = *(const float4*)(q + h * KS);
        float4 q1 = *(const float4*)(q + h * KS + 4);
        acc[0] += q0.x * q0.x; acc[1] += q0.y * q0.y;
        acc[2] += q0.z * q0.z; acc[3] += q0.w * q0.w;
        acc[4] += q1.x * q1.x; acc[5] += q1.y * q1.y;
        acc[6] += q1.z * q1.z; acc[7] += q1.w * q1.w;
    }

    __shared__ float red[KS * 256];
#pragma unroll
    for (int k = 0; k < KS; k++) red[k * 256 + tid] = acc[k];
    __syncthreads();
    for (int s = 128; s > 0; s >>= 1) {
        if (tid < s) {
#pragma unroll
            for (int k = 0; k < KS; k++)
                red[k * 256 + tid] += red[k * 256 + tid + s];
        }
        __syncthreads();
    }
    if (tid < KS)
        inv[b * KS + tid] = 1.0f / sqrtf(red[tid * 256]);
}

// ---------------------------------------------------------------------------
// Edge kernel v2: one warp per 8 edges (all in the same batch, since edges
// are batch-sorted and 8 | 512). q[h,0:8] is loaded ONCE per h per warp and
// reused across 8 edges -> q traffic drops 8x vs one-edge-per-warp.
// ---------------------------------------------------------------------------
#define EG 8
__global__ __launch_bounds__(128, 4)
void edge_kernel(const int* __restrict__ indexes,
                 const float* __restrict__ nh,
                 const float* __restrict__ qh,
                 const float* __restrict__ inv,
                 float* __restrict__ out)
{
    const int warp = blockIdx.x * (blockDim.x >> 5) + (threadIdx.x >> 5);
    const int lane = threadIdx.x & 31;
    const int m0   = warp * EG;
    if (m0 >= M_EDGE) return;

    // lanes 0..7 fetch the 8 edge indexes; broadcast via shfl
    int myidx = __ldg(indexes + m0 + (lane & (EG - 1)));

    int offS[EG], offD[EG];
#pragma unroll
    for (int e = 0; e < EG; e++) {
        int id  = __shfl_sync(0xFFFFFFFFu, myidx, e);
        int bb  = id >> 12;          // / 4096
        int rem = id & 4095;
        offS[e] = (((bb << 6) + (rem >> 6)) << 9);   // (b*64+src)*512
        offD[e] = (((bb << 6) + (rem & 63)) << 9);   // (b*64+dst)*512
    }
    const int b = (__shfl_sync(0xFFFFFFFFu, myidx, 0)) >> 12;
    const float* qb = qh + (size_t)b * HIDKS;

    float acc[EG][KS];
#pragma unroll
    for (int e = 0; e < EG; e++)
#pragma unroll
        for (int k = 0; k < KS; k++) acc[e][k] = 0.0f;

#pragma unroll 4
    for (int i = 0; i < HID / 32; i++) {
        const int h = lane + i * 32;
        float4 q0 = __ldg((const float4*)(qb + h * KS));
        float4 q1 = __ldg((const float4*)(qb + h * KS) + 1);
#pragma unroll
        for (int e = 0; e < EG; e++) {
            float o = __ldg(nh + offS[e] + h) + __ldg(nh + offD[e] + h);
            acc[e][0] += o * q0.x; acc[e][1] += o * q0.y;
            acc[e][2] += o * q0.z; acc[e][3] += o * q0.w;
            acc[e][4] += o * q1.x; acc[e][5] += o * q1.y;
            acc[e][6] += o * q1.z; acc[e][7] += o * q1.w;
        }
    }

    // Butterfly reduce each of the 64 partial sums across the warp
#pragma unroll
    for (int e = 0; e < EG; e++)
#pragma unroll
        for (int k = 0; k < KS; k++) {
            float v = acc[e][k];
            v += __shfl_xor_sync(0xFFFFFFFFu, v, 16);
            v += __shfl_xor_sync(0xFFFFFFFFu, v, 8);
            v += __shfl_xor_sync(0xFFFFFFFFu, v, 4);
            v += __shfl_xor_sync(0xFFFFFFFFu, v, 2);
            v += __shfl_xor_sync(0xFFFFFFFFu, v, 1);
            acc[e][k] = v;
        }

    const float4 i0 = *(const float4*)(inv + b * KS);
    const float4 i1 = *(const float4*)(inv + b * KS + 4);
#pragma unroll
    for (int e = 0; e < EG; e++) {
        if (lane == e) {
            float4 o0 = make_float4(acc[e][0] * i0.x, acc[e][1] * i0.y,
                                    acc[e][2] * i0.z, acc[e][3] * i0.w);
            float4 o1 = make_float4(acc[e][4] * i1.x, acc[e][5] * i1.y,
                                    acc[e][6] * i1.z, acc[e][7] * i1.w);
            ((float4*)out)[(size_t)(m0 + e) * 2]     = o0;
            ((float4*)out)[(size_t)(m0 + e) * 2 + 1] = o1;
        }
    }
}

// ---------------------------------------------------------------------------
extern "C" void kernel_launch(void* const* d_in, const int* in_sizes, int n_in,
                              void* d_out, int out_size)
{
    const float* node_feats = (const float*)d_in[0];   // [64,64,2048]
    const float* q_feats    = (const float*)d_in[1];   // [64,1024]
    const int*   indexes    = (const int*)d_in[2];     // [32768]
    const float* W_obj      = (const float*)d_in[3];   // [2048,512]
    const float* b_obj      = (const float*)d_in[4];   // [512]
    const float* W_q        = (const float*)d_in[5];   // [1024,4096]
    const float* b_q        = (const float*)d_in[6];   // [4096]
    float* out = (float*)d_out;                        // [32768,8]

    float *nh, *qh, *inv;
    cudaGetSymbolAddress((void**)&nh,  g_node_h);
    cudaGetSymbolAddress((void**)&qh,  g_q_h);
    cudaGetSymbolAddress((void**)&inv, g_inv_norm);

    // GEMM1: node_h[4096,512] = relu(node_feats @ W_obj + b_obj)
    {
        constexpr int BM = 128, BN = 128, BK = 32, WM = 2, WN = 4;
        constexpr int AP = BK + 4, BP = BN + 4;
        constexpr int SMEM_F = 2 * (BM * AP + BK * BP);
        constexpr int SMEM_C = BM * BP;
        constexpr int SMEM_B = ((SMEM_F > SMEM_C) ? SMEM_F : SMEM_C) * 4;
        static bool attr_set1 = false;
        if (!attr_set1) {
            cudaFuncSetAttribute(gemm_tf32_pipe<BM, BN, BK, WM, WN>,
                                 cudaFuncAttributeMaxDynamicSharedMemorySize, SMEM_B);
            attr_set1 = true;
        }
        gemm_tf32_pipe<BM, BN, BK, WM, WN>
            <<<dim3(HID / BN, (B_IMG * N_OBJ) / BM), WM * WN * 32, SMEM_B>>>(
                node_feats, W_obj, b_obj, nh, OBJDIM, HID);
    }
    // GEMM2: q_h[64,4096] = relu(q_feats @ W_q + b_q)
    {
        constexpr int BM = 64, BN = 64, BK = 32, WM = 2, WN = 2;
        constexpr int AP = BK + 4, BP = BN + 4;
        constexpr int SMEM_F = 2 * (BM * AP + BK * BP);
        constexpr int SMEM_C = BM * BP;
        constexpr int SMEM_B = ((SMEM_F > SMEM_C) ? SMEM_F : SMEM_C) * 4;
        static bool attr_set2 = false;
        if (!attr_set2) {
            cudaFuncSetAttribute(gemm_tf32_pipe<BM, BN, BK, WM, WN>,
                                 cudaFuncAttributeMaxDynamicSharedMemorySize, SMEM_B);
            attr_set2 = true;
        }
        gemm_tf32_pipe<BM, BN, BK, WM, WN>
            <<<dim3(HIDKS / BN, B_IMG / BM), WM * WN * 32, SMEM_B>>>(
                q_feats, W_q, b_q, qh, QDIM, HIDKS);
    }
    // Per-(batch,k) inverse norms
    qnorm_kernel<<<B_IMG, 256>>>(qh, inv);
    // Edge gather + dot + scale (8 edges per warp)
    edge_kernel<<<M_EDGE / (EG * 4), 128>>>(indexes, nh, qh, inv, out);
}

// round 4
// speedup vs baseline: 2.1623x; 2.0962x over previous
#include <cuda_runtime.h>
#include <cuda_bf16.h>
#include <mma.h>
#include <cstdint>

using namespace nvcuda;

// Problem constants
#define B_IMG   64
#define N_OBJ   64
#define M_EDGE  32768
#define OBJDIM  2048
#define QDIM    1024
#define KS      8
#define HID     512
#define HIDKS   4096

// Scratch (device globals; no cudaMalloc allowed)
__device__ __nv_bfloat16 g_nodeB[(size_t)4096 * OBJDIM];  // node_feats bf16
__device__ __nv_bfloat16 g_WobjB[(size_t)OBJDIM * HID];   // W_obj bf16
__device__ __nv_bfloat16 g_qB[(size_t)B_IMG * QDIM];      // q_feats bf16
__device__ __nv_bfloat16 g_WqB[(size_t)QDIM * HIDKS];     // W_q bf16
__device__ float g_node_h[(size_t)4096 * HID];            // [4096, 512]
__device__ float g_q_h[(size_t)B_IMG * HIDKS];            // [64, 4096]
__device__ float g_P[(size_t)B_IMG * N_OBJ * KS];         // [64, 64, 8]
__device__ float g_inv[B_IMG * KS];

// ---------------------------------------------------------------------------
// cp.async helpers
// ---------------------------------------------------------------------------
__device__ __forceinline__ uint32_t smem_u32(const void* p) {
    uint32_t a;
    asm("{ .reg .u64 t; cvta.to.shared.u64 t, %1; cvt.u32.u64 %0, t; }" : "=r"(a) : "l"(p));
    return a;
}
__device__ __forceinline__ void cp_async16(uint32_t dst, const void* src) {
    asm volatile("cp.async.cg.shared.global [%0], [%1], 16;\n" :: "r"(dst), "l"(src));
}
__device__ __forceinline__ void cp_commit() { asm volatile("cp.async.commit_group;\n"); }
template<int N> __device__ __forceinline__ void cp_wait() {
    asm volatile("cp.async.wait_group %0;\n" :: "n"(N));
}

// ---------------------------------------------------------------------------
// fp32 -> bf16 conversion (vectorized, grid-stride free: exact-size grids)
// ---------------------------------------------------------------------------
__global__ __launch_bounds__(256)
void cvt_bf16_kernel(const float* __restrict__ in, __nv_bfloat16* __restrict__ out)
{
    const int i = blockIdx.x * 256 + threadIdx.x;
    float4 v = ((const float4*)in)[i];
    __nv_bfloat162 a = __floats2bfloat162_rn(v.x, v.y);
    __nv_bfloat162 b = __floats2bfloat162_rn(v.z, v.w);
    ((__nv_bfloat162*)out)[i * 2]     = a;
    ((__nv_bfloat162*)out)[i * 2 + 1] = b;
}

// ---------------------------------------------------------------------------
// bf16 tensor-core GEMM, cp.async 3-stage pipeline, fused bias(col) + ReLU.
// C[M,N] = relu(A[M,K] @ B[K,N] + bias[N]).  A [M,K] row-major bf16,
// B [K,N] row-major bf16. wmma m16n16k16, warp tile (BM/WM)x(BN/WN).
// ---------------------------------------------------------------------------
template<int BM, int BN, int BK, int WM, int WN>
__global__ __launch_bounds__(WM * WN * 32)
void gemm_bf16(const __nv_bfloat16* __restrict__ A, const __nv_bfloat16* __restrict__ Bm,
               const float* __restrict__ bias, float* __restrict__ C,
               int Kdim, int Ndim)
{
    constexpr int NW = WM * WN;
    constexpr int NT = NW * 32;
    constexpr int FM = BM / WM / 16;
    constexpr int FN = BN / WN / 16;
    constexpr int S  = 3;
    constexpr int AP = BK + 8;                   // bf16 elems; 16B-aligned rows
    constexpr int BP = BN + 8;
    constexpr int ACH = BM * BK / 8;             // 16B chunks per A stage
    constexpr int BCH = BK * BN / 8;
    constexpr int PT  = (ACH + BCH) / NT;
    static_assert(PT * NT == ACH + BCH, "chunk split");
    constexpr int STA = BM * AP * 2;             // bytes per A stage
    constexpr int STB = BK * BP * 2;
    constexpr int CP  = BN + 4;                  // epilogue float stride

    extern __shared__ __align__(16) char smem[];
    const uint32_t sA = smem_u32(smem);
    const uint32_t sB = sA + S * STA;

    const int tid  = threadIdx.x;
    const int wid  = tid >> 5;
    const int wm   = wid % WM;
    const int wn   = wid / WM;
    const int bM   = blockIdx.y * BM;
    const int bN   = blockIdx.x * BN;
    const int NIT  = Kdim / BK;

    auto load_slab = [&](int slab) {
        const int s  = slab % S;
        const int k0 = slab * BK;
#pragma unroll
        for (int t = 0; t < PT; t++) {
            int l = tid + t * NT;
            if (l < ACH) {
                int r = l / (BK / 8), c = l % (BK / 8);
                cp_async16(sA + s * STA + (r * AP + c * 8) * 2,
                           A + (size_t)(bM + r) * Kdim + k0 + c * 8);
            } else {
                int l2 = l - ACH;
                int r = l2 / (BN / 8), c = l2 % (BN / 8);
                cp_async16(sB + s * STB + (r * BP + c * 8) * 2,
                           Bm + (size_t)(k0 + r) * Ndim + bN + c * 8);
            }
        }
    };

    wmma::fragment<wmma::accumulator, 16, 16, 16, float> acc[FM][FN];
#pragma unroll
    for (int i = 0; i < FM; i++)
#pragma unroll
        for (int j = 0; j < FN; j++)
            wmma::fill_fragment(acc[i][j], 0.0f);

#pragma unroll
    for (int s = 0; s < S; s++) { load_slab(s); cp_commit(); }

    for (int i = 0; i < NIT; i++) {
        cp_wait<S - 2>();
        __syncthreads();
        if (i >= 1) {
            int j = i - 1 + S;
            if (j < NIT) load_slab(j);   // into slot (i-1)%S, freed by compute i-1
            cp_commit();                  // unconditional: keeps wait<S-2> math uniform
        }
        const __nv_bfloat16* as = (const __nv_bfloat16*)(smem + (size_t)(i % S) * STA);
        const __nv_bfloat16* bs = (const __nv_bfloat16*)(smem + (size_t)S * STA + (size_t)(i % S) * STB);
#pragma unroll
        for (int kk = 0; kk < BK / 16; kk++) {
            wmma::fragment<wmma::matrix_a, 16, 16, 16, __nv_bfloat16, wmma::row_major> af[FM];
            wmma::fragment<wmma::matrix_b, 16, 16, 16, __nv_bfloat16, wmma::row_major> bf[FN];
#pragma unroll
            for (int f = 0; f < FM; f++)
                wmma::load_matrix_sync(af[f], as + (wm * FM * 16 + f * 16) * AP + kk * 16, AP);
#pragma unroll
            for (int j = 0; j < FN; j++)
                wmma::load_matrix_sync(bf[j], bs + (kk * 16) * BP + wn * FN * 16 + j * 16, BP);
#pragma unroll
            for (int f = 0; f < FM; f++)
#pragma unroll
                for (int j = 0; j < FN; j++)
                    wmma::mma_sync(acc[f][j], af[f], bf[j], acc[f][j]);
        }
    }

    // Epilogue: frags -> smem(float) -> fused bias+ReLU vectorized store
    __syncthreads();
    float* Cs = (float*)smem;
#pragma unroll
    for (int f = 0; f < FM; f++)
#pragma unroll
        for (int j = 0; j < FN; j++)
            wmma::store_matrix_sync(Cs + (wm * FM * 16 + f * 16) * CP + wn * FN * 16 + j * 16,
                                    acc[f][j], CP, wmma::mem_row_major);
    __syncthreads();
#pragma unroll
    for (int t = 0; t < (BM * BN / 4) / NT; t++) {
        int l = tid + t * NT;
        int r = l / (BN / 4);
        int c = l % (BN / 4);
        float4 v  = *(float4*)(Cs + r * CP + c * 4);
        float4 bb = __ldg((const float4*)(bias + bN + c * 4));
        v.x = fmaxf(v.x + bb.x, 0.0f);
        v.y = fmaxf(v.y + bb.y, 0.0f);
        v.z = fmaxf(v.z + bb.z, 0.0f);
        v.w = fmaxf(v.w + bb.w, 0.0f);
        *(float4*)(C + (size_t)(bM + r) * Ndim + bN + c * 4) = v;
    }
}

// ---------------------------------------------------------------------------
// Per-(batch, k) inverse norm: inv[b,k] = 1/sqrt(sum_h q_h[b, h*KS+k]^2)
// ---------------------------------------------------------------------------
__global__ __launch_bounds__(256)
void qnorm_kernel(const float* __restrict__ qh, float* __restrict__ inv)
{
    const int b   = blockIdx.x;
    const int tid = threadIdx.x;
    const float* q = qh + (size_t)b * HIDKS;

    float acc[KS];
#pragma unroll
    for (int k = 0; k < KS; k++) acc[k] = 0.0f;
    for (int h = tid; h < HID; h += 256) {
        float4 q0 = *(const float4*)(q + h * KS);
        float4 q1 = *(const float4*)(q + h * KS + 4);
        acc[0] += q0.x * q0.x; acc[1] += q0.y * q0.y;
        acc[2] += q0.z * q0.z; acc[3] += q0.w * q0.w;
        acc[4] += q1.x * q1.x; acc[5] += q1.y * q1.y;
        acc[6] += q1.z * q1.z; acc[7] += q1.w * q1.w;
    }
    __shared__ float red[KS * 256];
#pragma unroll
    for (int k = 0; k < KS; k++) red[k * 256 + tid] = acc[k];
    __syncthreads();
    for (int s = 128; s > 0; s >>= 1) {
        if (tid < s) {
#pragma unroll
            for (int k = 0; k < KS; k++)
                red[k * 256 + tid] += red[k * 256 + tid + s];
        }
        __syncthreads();
    }
    if (tid < KS)
        inv[b * KS + tid] = 1.0f / sqrtf(red[tid * 256]);
}

// ---------------------------------------------------------------------------
// P[b,n,k] = sum_h node_h[b,n,h] * q_h[b, h*KS + k].  One block per batch.
// 256 threads = 64 nodes x 4 h-quarters.
// ---------------------------------------------------------------------------
__global__ __launch_bounds__(256)
void p_kernel(const float* __restrict__ nh, const float* __restrict__ qh,
              float* __restrict__ P)
{
    __shared__ float qs[HIDKS];                  // 16 KB
    const int b   = blockIdx.x;
    const int tid = threadIdx.x;
    const float4* qsrc = (const float4*)(qh + (size_t)b * HIDKS);
#pragma unroll
    for (int i = 0; i < HIDKS / 4 / 256; i++)
        ((float4*)qs)[tid + i * 256] = qsrc[tid + i * 256];
    __syncthreads();

    const int n  = tid >> 2;
    const int qq = tid & 3;
    const float4* row = (const float4*)(nh + (size_t)(b * N_OBJ + n) * HID + qq * 128);

    float acc[KS];
#pragma unroll
    for (int k = 0; k < KS; k++) acc[k] = 0.0f;
#pragma unroll 8
    for (int i = 0; i < 32; i++) {
        float4 v = row[i];
        const float* qp = qs + (qq * 128 + i * 4) * KS;
#pragma unroll
        for (int e = 0; e < 4; e++) {
            float o = (&v.x)[e];
            float4 a0 = *(const float4*)(qp + e * KS);
            float4 a1 = *(const float4*)(qp + e * KS + 4);
            acc[0] += o * a0.x; acc[1] += o * a0.y;
            acc[2] += o * a0.z; acc[3] += o * a0.w;
            acc[4] += o * a1.x; acc[5] += o * a1.y;
            acc[6] += o * a1.z; acc[7] += o * a1.w;
        }
    }
#pragma unroll
    for (int k = 0; k < KS; k++) {
        acc[k] += __shfl_xor_sync(0xFFFFFFFFu, acc[k], 1);
        acc[k] += __shfl_xor_sync(0xFFFFFFFFu, acc[k], 2);
    }
    if (qq == 0) {
        float* dst = P + (size_t)(b * N_OBJ + n) * KS;
        *(float4*)dst       = make_float4(acc[0], acc[1], acc[2], acc[3]);
        *(float4*)(dst + 4) = make_float4(acc[4], acc[5], acc[6], acc[7]);
    }
}

// ---------------------------------------------------------------------------
// out[m, k] = (P[b,src,k] + P[b,dst,k]) * inv[b,k]   (one thread per edge)
// ---------------------------------------------------------------------------
__global__ __launch_bounds__(256)
void gather_kernel(const int* __restrict__ idxs, const float* __restrict__ P,
                   const float* __restrict__ inv, float* __restrict__ out)
{
    const int m = blockIdx.x * 256 + threadIdx.x;
    const int idx = __ldg(idxs + m);
    const int b = idx >> 12, rem = idx & 4095;
    const int src = rem >> 6, dst = rem & 63;
    const float4* ps = (const float4*)(P + (size_t)(b * N_OBJ + src) * KS);
    const float4* pd = (const float4*)(P + (size_t)(b * N_OBJ + dst) * KS);
    const float4* iv = (const float4*)(inv + b * KS);
    float4 s0 = ps[0], s1 = ps[1], d0 = pd[0], d1 = pd[1], i0 = iv[0], i1 = iv[1];
    float4 o0 = make_float4((s0.x + d0.x) * i0.x, (s0.y + d0.y) * i0.y,
                            (s0.z + d0.z) * i0.z, (s0.w + d0.w) * i0.w);
    float4 o1 = make_float4((s1.x + d1.x) * i1.x, (s1.y + d1.y) * i1.y,
                            (s1.z + d1.z) * i1.z, (s1.w + d1.w) * i1.w);
    ((float4*)out)[(size_t)m * 2]     = o0;
    ((float4*)out)[(size_t)m * 2 + 1] = o1;
}

// ---------------------------------------------------------------------------
extern "C" void kernel_launch(void* const* d_in, const int* in_sizes, int n_in,
                              void* d_out, int out_size)
{
    const float* node_feats = (const float*)d_in[0];   // [64,64,2048]
    const float* q_feats    = (const float*)d_in[1];   // [64,1024]
    const int*   indexes    = (const int*)d_in[2];     // [32768]
    const float* W_obj      = (const float*)d_in[3];   // [2048,512]
    const float* b_obj      = (const float*)d_in[4];   // [512]
    const float* W_q        = (const float*)d_in[5];   // [1024,4096]
    const float* b_q        = (const float*)d_in[6];   // [4096]
    float* out = (float*)d_out;                        // [32768,8]

    __nv_bfloat16 *nodeB, *wobjB, *qB, *wqB;
    float *nh, *qh, *P, *inv;
    cudaGetSymbolAddress((void**)&nodeB, g_nodeB);
    cudaGetSymbolAddress((void**)&wobjB, g_WobjB);
    cudaGetSymbolAddress((void**)&qB,    g_qB);
    cudaGetSymbolAddress((void**)&wqB,   g_WqB);
    cudaGetSymbolAddress((void**)&nh,    g_node_h);
    cudaGetSymbolAddress((void**)&qh,    g_q_h);
    cudaGetSymbolAddress((void**)&P,     g_P);
    cudaGetSymbolAddress((void**)&inv,   g_inv);

    // fp32 -> bf16 conversions
    cvt_bf16_kernel<<<(4096 * OBJDIM) / 1024, 256>>>(node_feats, nodeB);
    cvt_bf16_kernel<<<(OBJDIM * HID) / 1024, 256>>>(W_obj, wobjB);
    cvt_bf16_kernel<<<(B_IMG * QDIM) / 1024, 256>>>(q_feats, qB);
    cvt_bf16_kernel<<<(QDIM * HIDKS) / 1024, 256>>>(W_q, wqB);

    // GEMM1: node_h[4096,512] = relu(node_feats @ W_obj + b_obj)
    {
        constexpr int BM = 128, BN = 128, BK = 64, WM = 2, WN = 4;
        constexpr int SM_PIPE = 3 * (BM * (BK + 8) * 2) + 3 * (BK * (BN + 8) * 2);
        constexpr int SM_EPI  = BM * (BN + 4) * 4;
        constexpr int SM = (SM_PIPE > SM_EPI ? SM_PIPE : SM_EPI);
        cudaFuncSetAttribute(gemm_bf16<BM, BN, BK, WM, WN>,
                             cudaFuncAttributeMaxDynamicSharedMemorySize, SM);
        gemm_bf16<BM, BN, BK, WM, WN>
            <<<dim3(HID / BN, 4096 / BM), WM * WN * 32, SM>>>(
                nodeB, wobjB, b_obj, nh, OBJDIM, HID);
    }
    // GEMM2: q_h[64,4096] = relu(q_feats @ W_q + b_q)
    {
        constexpr int BM = 64, BN = 64, BK = 64, WM = 2, WN = 2;
        constexpr int SM_PIPE = 3 * (BM * (BK + 8) * 2) + 3 * (BK * (BN + 8) * 2);
        constexpr int SM_EPI  = BM * (BN + 4) * 4;
        constexpr int SM = (SM_PIPE > SM_EPI ? SM_PIPE : SM_EPI);
        cudaFuncSetAttribute(gemm_bf16<BM, BN, BK, WM, WN>,
                             cudaFuncAttributeMaxDynamicSharedMemorySize, SM);
        gemm_bf16<BM, BN, BK, WM, WN>
            <<<dim3(HIDKS / BN, B_IMG / BM), WM * WN * 32, SM>>>(
                qB, wqB, b_q, qh, QDIM, HIDKS);
    }
    // Per-(batch,k) inverse norms
    qnorm_kernel<<<B_IMG, 256>>>(qh, inv);
    // P[b,n,k] = node_h[b,n,:] . q_h[b, :*8+k]
    p_kernel<<<B_IMG, 256>>>(nh, qh, P);
    // Edge gather: out = (P[src] + P[dst]) * inv
    gather_kernel<<<M_EDGE / 256, 256>>>(indexes, P, inv, out);
}

// round 5
// speedup vs baseline: 2.7209x; 1.2584x over previous
#include <cuda_runtime.h>
#include <cuda_bf16.h>
#include <mma.h>
#include <cstdint>

using namespace nvcuda;

// Problem constants
#define B_IMG   64
#define N_OBJ   64
#define M_EDGE  32768
#define OBJDIM  2048
#define QDIM    1024
#define KS      8
#define HID     512
#define HIDKS   4096

// Scratch (device globals; no cudaMalloc allowed)
__device__ __nv_bfloat16 g_nodeB[(size_t)4096 * OBJDIM];
__device__ __nv_bfloat16 g_WobjB[(size_t)OBJDIM * HID];
__device__ __nv_bfloat16 g_qB[(size_t)B_IMG * QDIM];
__device__ __nv_bfloat16 g_WqB[(size_t)QDIM * HIDKS];
__device__ float g_q_h[(size_t)B_IMG * HIDKS];           // [64, 4096]
__device__ float g_P8[(size_t)8 * 4096 * KS];            // per-Ntile P partials
__device__ float g_P[(size_t)4096 * KS];                 // [4096, 8]
__device__ float g_norm8[(size_t)64 * B_IMG * KS];       // per-Ntile norm partials
__device__ float g_inv[B_IMG * KS];

// ---------------------------------------------------------------------------
__device__ __forceinline__ uint32_t smem_u32(const void* p) {
    uint32_t a;
    asm("{ .reg .u64 t; cvta.to.shared.u64 t, %1; cvt.u32.u64 %0, t; }" : "=r"(a) : "l"(p));
    return a;
}
__device__ __forceinline__ void cp_async16(uint32_t dst, const void* src) {
    asm volatile("cp.async.cg.shared.global [%0], [%1], 16;\n" :: "r"(dst), "l"(src));
}
__device__ __forceinline__ void cp_commit() { asm volatile("cp.async.commit_group;\n"); }
template<int N> __device__ __forceinline__ void cp_wait() {
    asm volatile("cp.async.wait_group %0;\n" :: "n"(N));
}

// ---------------------------------------------------------------------------
// Fused fp32 -> bf16 conversion for all 4 inputs (one launch)
// grid = 8192 (node) + 1024 (W_obj) + 64 (q) + 4096 (W_q) = 13376 blocks
// ---------------------------------------------------------------------------
__global__ __launch_bounds__(256)
void cvt_all_kernel(const float* __restrict__ nf, const float* __restrict__ wo,
                    const float* __restrict__ qf, const float* __restrict__ wq,
                    __nv_bfloat16* __restrict__ nodeB, __nv_bfloat16* __restrict__ wobjB,
                    __nv_bfloat16* __restrict__ qB, __nv_bfloat16* __restrict__ wqB)
{
    const int bid = blockIdx.x;
    const float* src; __nv_bfloat16* dst; int lb;
    if (bid < 8192)      { src = nf; dst = nodeB; lb = bid; }
    else if (bid < 9216) { src = wo; dst = wobjB; lb = bid - 8192; }
    else if (bid < 9280) { src = qf; dst = qB;    lb = bid - 9216; }
    else                 { src = wq; dst = wqB;   lb = bid - 9280; }
    const int i = lb * 256 + threadIdx.x;
    float4 v = ((const float4*)src)[i];
    ((__nv_bfloat162*)dst)[i * 2]     = __floats2bfloat162_rn(v.x, v.y);
    ((__nv_bfloat162*)dst)[i * 2 + 1] = __floats2bfloat162_rn(v.z, v.w);
}

// ---------------------------------------------------------------------------
// GEMM2: q_h[64,4096] = relu(q_feats @ W_q + b_q), fused norm partials.
// BM=64, BN=64, BK=64, 4 warps (WM=2,WN=2), 3-stage cp.async pipeline.
// grid = (64, 1): ntile = blockIdx.x. Writes norm8[ntile][b][k] (exclusive).
// ---------------------------------------------------------------------------
__global__ __launch_bounds__(128)
void gemm2_kernel(const __nv_bfloat16* __restrict__ A, const __nv_bfloat16* __restrict__ Bm,
                  const float* __restrict__ bias, float* __restrict__ C,
                  float* __restrict__ norm8)
{
    constexpr int BM = 64, BN = 64, BK = 64, S = 3;
    constexpr int AP = BK + 8, BP = BN + 8;
    constexpr int STA = BM * AP * 2, STB = BK * BP * 2;
    constexpr int ACH = BM * BK / 8, BCH = BK * BN / 8;    // 512 + 512
    constexpr int PT = (ACH + BCH) / 128;                  // 8
    constexpr int NIT = QDIM / BK;                         // 16
    constexpr int CP = BN + 4;

    extern __shared__ __align__(16) char smem[];
    const uint32_t sA = smem_u32(smem);
    const uint32_t sB = sA + S * STA;

    const int tid = threadIdx.x;
    const int wid = tid >> 5;
    const int wm = wid & 1, wn = wid >> 1;
    const int bN = blockIdx.x * BN;

    auto load_slab = [&](int slab) {
        const int s = slab % S, k0 = slab * BK;
#pragma unroll
        for (int t = 0; t < PT; t++) {
            int l = tid + t * 128;
            if (l < ACH) {
                int r = l >> 3, c = l & 7;
                cp_async16(sA + s * STA + (r * AP + c * 8) * 2,
                           A + (size_t)r * QDIM + k0 + c * 8);
            } else {
                int l2 = l - ACH;
                int r = l2 >> 3, c = l2 & 7;
                cp_async16(sB + s * STB + (r * BP + c * 8) * 2,
                           Bm + (size_t)(k0 + r) * HIDKS + bN + c * 8);
            }
        }
    };

    wmma::fragment<wmma::accumulator, 16, 16, 16, float> acc[2][2];
#pragma unroll
    for (int i = 0; i < 2; i++)
#pragma unroll
        for (int j = 0; j < 2; j++) wmma::fill_fragment(acc[i][j], 0.0f);

#pragma unroll
    for (int s = 0; s < S; s++) { load_slab(s); cp_commit(); }

    for (int i = 0; i < NIT; i++) {
        cp_wait<S - 2>();
        __syncthreads();
        if (i >= 1) {
            int j = i - 1 + S;
            if (j < NIT) load_slab(j);
            cp_commit();
        }
        const __nv_bfloat16* as = (const __nv_bfloat16*)(smem + (size_t)(i % S) * STA);
        const __nv_bfloat16* bs = (const __nv_bfloat16*)(smem + (size_t)S * STA + (size_t)(i % S) * STB);
#pragma unroll
        for (int kk = 0; kk < BK / 16; kk++) {
            wmma::fragment<wmma::matrix_a, 16, 16, 16, __nv_bfloat16, wmma::row_major> af[2];
            wmma::fragment<wmma::matrix_b, 16, 16, 16, __nv_bfloat16, wmma::row_major> bf[2];
#pragma unroll
            for (int f = 0; f < 2; f++)
                wmma::load_matrix_sync(af[f], as + (wm * 32 + f * 16) * AP + kk * 16, AP);
#pragma unroll
            for (int j = 0; j < 2; j++)
                wmma::load_matrix_sync(bf[j], bs + (kk * 16) * BP + wn * 32 + j * 16, BP);
#pragma unroll
            for (int f = 0; f < 2; f++)
#pragma unroll
                for (int j = 0; j < 2; j++)
                    wmma::mma_sync(acc[f][j], af[f], bf[j], acc[f][j]);
        }
    }

    __syncthreads();
    float* Cs = (float*)smem;                    // 64 x 68 floats = 17408 B
    float* biasS = Cs + BM * CP;                 // 64 floats
#pragma unroll
    for (int f = 0; f < 2; f++)
#pragma unroll
        for (int j = 0; j < 2; j++)
            wmma::store_matrix_sync(Cs + (wm * 32 + f * 16) * CP + wn * 32 + j * 16,
                                    acc[f][j], CP, wmma::mem_row_major);
    if (tid < BN) biasS[tid] = bias[bN + tid];
    __syncthreads();

    // Write q_h with bias+relu
#pragma unroll
    for (int t = 0; t < (BM * BN / 4) / 128; t++) {
        int l = tid + t * 128;
        int r = l >> 4, c4 = (l & 15) * 4;
        float4 v = *(float4*)(Cs + r * CP + c4);
        v.x = fmaxf(v.x + biasS[c4 + 0], 0.0f);
        v.y = fmaxf(v.y + biasS[c4 + 1], 0.0f);
        v.z = fmaxf(v.z + biasS[c4 + 2], 0.0f);
        v.w = fmaxf(v.w + biasS[c4 + 3], 0.0f);
        *(float4*)(C + (size_t)r * HIDKS + bN + c4) = v;
    }
    // Norm partials: one thread per batch row (exclusive writes)
    if (tid < BM) {
        float a[KS];
#pragma unroll
        for (int k = 0; k < KS; k++) a[k] = 0.0f;
#pragma unroll
        for (int c0 = 0; c0 < 8; c0++)
#pragma unroll
            for (int j = 0; j < 8; j++) {
                float v = fmaxf(Cs[tid * CP + c0 * 8 + j] + biasS[c0 * 8 + j], 0.0f);
                a[j] += v * v;
            }
        float* dst = norm8 + (size_t)blockIdx.x * (B_IMG * KS) + tid * KS;
        *(float4*)dst       = make_float4(a[0], a[1], a[2], a[3]);
        *(float4*)(dst + 4) = make_float4(a[4], a[5], a[6], a[7]);
    }
}

// ---------------------------------------------------------------------------
// GEMM1 fused: C-tile = node_feats @ W_obj (+bias, relu) computed in smem,
// immediately contracted against q_h -> P8[ntile][row][k]. node_h never hits
// global memory. BM=128, BN=64, BK=64, 8 warps (WM=4,WN=2), 3 stages.
// grid = (8, 32); 2 CTAs/SM.
// ---------------------------------------------------------------------------
__global__ __launch_bounds__(256, 2)
void gemm1_kernel(const __nv_bfloat16* __restrict__ A, const __nv_bfloat16* __restrict__ Bm,
                  const float* __restrict__ bias, const float* __restrict__ qh,
                  float* __restrict__ P8)
{
    constexpr int BM = 128, BN = 64, BK = 64, S = 3;
    constexpr int AP = BK + 8, BP = BN + 8;
    constexpr int STA = BM * AP * 2, STB = BK * BP * 2;    // 18432, 9216
    constexpr int ACH = BM * BK / 8, BCH = BK * BN / 8;    // 1024, 512
    constexpr int PT = (ACH + BCH) / 256;                  // 6
    constexpr int NIT = OBJDIM / BK;                       // 32
    constexpr int CP = BN + 4;                             // 68

    extern __shared__ __align__(16) char smem[];
    const uint32_t sA = smem_u32(smem);
    const uint32_t sB = sA + S * STA;

    const int tid = threadIdx.x;
    const int wid = tid >> 5;
    const int wm = wid & 3, wn = wid >> 2;
    const int bM = blockIdx.y * BM;
    const int bN = blockIdx.x * BN;

    auto load_slab = [&](int slab) {
        const int s = slab % S, k0 = slab * BK;
#pragma unroll
        for (int t = 0; t < PT; t++) {
            int l = tid + t * 256;
            if (l < ACH) {
                int r = l >> 3, c = l & 7;
                cp_async16(sA + s * STA + (r * AP + c * 8) * 2,
                           A + (size_t)(bM + r) * OBJDIM + k0 + c * 8);
            } else {
                int l2 = l - ACH;
                int r = l2 >> 3, c = l2 & 7;
                cp_async16(sB + s * STB + (r * BP + c * 8) * 2,
                           Bm + (size_t)(k0 + r) * HID + bN + c * 8);
            }
        }
    };

    wmma::fragment<wmma::accumulator, 16, 16, 16, float> acc[2][2];
#pragma unroll
    for (int i = 0; i < 2; i++)
#pragma unroll
        for (int j = 0; j < 2; j++) wmma::fill_fragment(acc[i][j], 0.0f);

#pragma unroll
    for (int s = 0; s < S; s++) { load_slab(s); cp_commit(); }

    for (int i = 0; i < NIT; i++) {
        cp_wait<S - 2>();
        __syncthreads();
        if (i >= 1) {
            int j = i - 1 + S;
            if (j < NIT) load_slab(j);
            cp_commit();
        }
        const __nv_bfloat16* as = (const __nv_bfloat16*)(smem + (size_t)(i % S) * STA);
        const __nv_bfloat16* bs = (const __nv_bfloat16*)(smem + (size_t)S * STA + (size_t)(i % S) * STB);
#pragma unroll
        for (int kk = 0; kk < BK / 16; kk++) {
            wmma::fragment<wmma::matrix_a, 16, 16, 16, __nv_bfloat16, wmma::row_major> af[2];
            wmma::fragment<wmma::matrix_b, 16, 16, 16, __nv_bfloat16, wmma::row_major> bf[2];
#pragma unroll
            for (int f = 0; f < 2; f++)
                wmma::load_matrix_sync(af[f], as + (wm * 32 + f * 16) * AP + kk * 16, AP);
#pragma unroll
            for (int j = 0; j < 2; j++)
                wmma::load_matrix_sync(bf[j], bs + (kk * 16) * BP + wn * 32 + j * 16, BP);
#pragma unroll
            for (int f = 0; f < 2; f++)
#pragma unroll
                for (int j = 0; j < 2; j++)
                    wmma::mma_sync(acc[f][j], af[f], bf[j], acc[f][j]);
        }
    }

    // Epilogue: C tile -> smem, then contract vs q_h into P8 (exclusive writes)
    __syncthreads();
    float* Cs    = (float*)smem;                 // 128 x 68 = 34816 B
    float* qs    = Cs + BM * CP;                 // 2 x 512 floats = 4096 B
    float* biasS = qs + 2 * 512;                 // 64 floats
#pragma unroll
    for (int f = 0; f < 2; f++)
#pragma unroll
        for (int j = 0; j < 2; j++)
            wmma::store_matrix_sync(Cs + (wm * 32 + f * 16) * CP + wn * 32 + j * 16,
                                    acc[f][j], CP, wmma::mem_row_major);
    {   // stage q_h segments for the two batches covered by this M-tile
        const int bB0 = bM >> 6;                 // first batch index (2 per tile)
        const int s = tid >> 7, i4 = (tid & 127) * 4;
        *(float4*)(qs + s * 512 + i4) =
            *(const float4*)(qh + (size_t)(bB0 + s) * HIDKS + bN * KS + i4);
        if (tid < BN) biasS[tid] = bias[bN + tid];
    }
    __syncthreads();

    const int r = tid >> 1, half = tid & 1;
    const int grow = bM + r;
    const float* qsp = qs + (r >> 6) * 512 + half * 4;
    float a0 = 0.f, a1 = 0.f, a2 = 0.f, a3 = 0.f;
#pragma unroll 8
    for (int c = 0; c < BN; c++) {
        float v = fmaxf(Cs[r * CP + c] + biasS[c], 0.0f);
        float4 qv = *(const float4*)(qsp + c * 8);
        a0 += v * qv.x; a1 += v * qv.y; a2 += v * qv.z; a3 += v * qv.w;
    }
    *(float4*)(P8 + (size_t)blockIdx.x * (4096 * KS) + (size_t)grow * KS + half * 4)
        = make_float4(a0, a1, a2, a3);
}

// ---------------------------------------------------------------------------
// Finalize: P = sum_nt P8[nt];  inv = rsqrt(sum_nt norm8[nt])
// grid = 130 x 256  (32768 P elems + 512 inv elems)
// ---------------------------------------------------------------------------
__global__ __launch_bounds__(256)
void finalize_kernel(const float* __restrict__ P8, float* __restrict__ P,
                     const float* __restrict__ norm8, float* __restrict__ inv)
{
    const int gid = blockIdx.x * 256 + threadIdx.x;
    if (gid < 4096 * KS) {
        float s = 0.f;
#pragma unroll
        for (int nt = 0; nt < 8; nt++) s += P8[nt * 4096 * KS + gid];
        P[gid] = s;
    } else if (gid < 4096 * KS + B_IMG * KS) {
        const int i = gid - 4096 * KS;
        float s = 0.f;
#pragma unroll
        for (int nt = 0; nt < 64; nt++) s += norm8[nt * (B_IMG * KS) + i];
        inv[i] = rsqrtf(s);
    }
}

// ---------------------------------------------------------------------------
// out[m, k] = (P[b,src,k] + P[b,dst,k]) * inv[b,k]
// ---------------------------------------------------------------------------
__global__ __launch_bounds__(256)
void gather_kernel(const int* __restrict__ idxs, const float* __restrict__ P,
                   const float* __restrict__ inv, float* __restrict__ out)
{
    const int m = blockIdx.x * 256 + threadIdx.x;
    const int idx = __ldg(idxs + m);
    const int b = idx >> 12, rem = idx & 4095;
    const int src = rem >> 6, dst = rem & 63;
    const float4* ps = (const float4*)(P + (size_t)(b * N_OBJ + src) * KS);
    const float4* pd = (const float4*)(P + (size_t)(b * N_OBJ + dst) * KS);
    const float4* iv = (const float4*)(inv + b * KS);
    float4 s0 = ps[0], s1 = ps[1], d0 = pd[0], d1 = pd[1], i0 = iv[0], i1 = iv[1];
    float4 o0 = make_float4((s0.x + d0.x) * i0.x, (s0.y + d0.y) * i0.y,
                            (s0.z + d0.z) * i0.z, (s0.w + d0.w) * i0.w);
    float4 o1 = make_float4((s1.x + d1.x) * i1.x, (s1.y + d1.y) * i1.y,
                            (s1.z + d1.z) * i1.z, (s1.w + d1.w) * i1.w);
    ((float4*)out)[(size_t)m * 2]     = o0;
    ((float4*)out)[(size_t)m * 2 + 1] = o1;
}

// ---------------------------------------------------------------------------
extern "C" void kernel_launch(void* const* d_in, const int* in_sizes, int n_in,
                              void* d_out, int out_size)
{
    const float* node_feats = (const float*)d_in[0];
    const float* q_feats    = (const float*)d_in[1];
    const int*   indexes    = (const int*)d_in[2];
    const float* W_obj      = (const float*)d_in[3];
    const float* b_obj      = (const float*)d_in[4];
    const float* W_q        = (const float*)d_in[5];
    const float* b_q        = (const float*)d_in[6];
    float* out = (float*)d_out;

    __nv_bfloat16 *nodeB, *wobjB, *qB, *wqB;
    float *qh, *P8, *P, *norm8, *inv;
    cudaGetSymbolAddress((void**)&nodeB, g_nodeB);
    cudaGetSymbolAddress((void**)&wobjB, g_WobjB);
    cudaGetSymbolAddress((void**)&qB,    g_qB);
    cudaGetSymbolAddress((void**)&wqB,   g_WqB);
    cudaGetSymbolAddress((void**)&qh,    g_q_h);
    cudaGetSymbolAddress((void**)&P8,    g_P8);
    cudaGetSymbolAddress((void**)&P,     g_P);
    cudaGetSymbolAddress((void**)&norm8, g_norm8);
    cudaGetSymbolAddress((void**)&inv,   g_inv);

    // 1) all fp32 -> bf16 conversions, one launch
    cvt_all_kernel<<<13376, 256>>>(node_feats, W_obj, q_feats, W_q,
                                   nodeB, wobjB, qB, wqB);

    // 2) GEMM2 + norm partials (must precede GEMM1: epilogue consumes q_h)
    {
        constexpr int SM = 3 * (64 * 72 * 2 + 64 * 72 * 2);      // 55296
        cudaFuncSetAttribute(gemm2_kernel, cudaFuncAttributeMaxDynamicSharedMemorySize, SM);
        gemm2_kernel<<<dim3(HIDKS / 64, 1), 128, SM>>>(qB, wqB, b_q, qh, norm8);
    }
    // 3) GEMM1 fused with P contraction
    {
        constexpr int SM = 3 * (128 * 72 * 2 + 64 * 72 * 2);     // 82944
        cudaFuncSetAttribute(gemm1_kernel, cudaFuncAttributeMaxDynamicSharedMemorySize, SM);
        gemm1_kernel<<<dim3(HID / 64, 4096 / 128), 256, SM>>>(nodeB, wobjB, b_obj, qh, P8);
    }
    // 4) reduce partials
    finalize_kernel<<<130, 256>>>(P8, P, norm8, inv);
    // 5) edge gather
    gather_kernel<<<M_EDGE / 256, 256>>>(indexes, P, inv, out);
}

// round 7
// speedup vs baseline: 3.0551x; 1.1228x over previous
#include <cuda_runtime.h>
#include <cuda_bf16.h>
#include <mma.h>
#include <cstdint>

using namespace nvcuda;

// Problem constants
#define B_IMG   64
#define N_OBJ   64
#define M_EDGE  32768
#define OBJDIM  2048
#define QDIM    1024
#define KS      8
#define HID     512
#define HIDKS   4096

// Scratch (device globals; no cudaMalloc allowed)
__device__ __nv_bfloat16 g_nodeB[(size_t)4096 * OBJDIM];
__device__ __nv_bfloat16 g_WobjB[(size_t)OBJDIM * HID];
__device__ __nv_bfloat16 g_qB[(size_t)B_IMG * QDIM];
__device__ __nv_bfloat16 g_WqB[(size_t)QDIM * HIDKS];
__device__ float g_q_h[(size_t)B_IMG * HIDKS];           // [64, 4096]
__device__ float g_P8[(size_t)8 * 4096 * KS];            // per-Ntile P partials
__device__ float g_P[(size_t)4096 * KS];                 // [4096, 8]
__device__ float g_norm8[(size_t)64 * B_IMG * KS];       // per-Ntile norm partials
__device__ float g_inv[B_IMG * KS];

// ---------------------------------------------------------------------------
__device__ __forceinline__ uint32_t smem_u32(const void* p) {
    uint32_t a;
    asm("{ .reg .u64 t; cvta.to.shared.u64 t, %1; cvt.u32.u64 %0, t; }" : "=r"(a) : "l"(p));
    return a;
}
__device__ __forceinline__ void cp_async16(uint32_t dst, const void* src) {
    asm volatile("cp.async.cg.shared.global [%0], [%1], 16;\n" :: "r"(dst), "l"(src));
}
__device__ __forceinline__ void cp_commit() { asm volatile("cp.async.commit_group;\n"); }
template<int N> __device__ __forceinline__ void cp_wait() {
    asm volatile("cp.async.wait_group %0;\n" :: "n"(N));
}

// ---------------------------------------------------------------------------
// Fused fp32 -> bf16 conversion, 32B read / 16B write per thread.
// grid = 4096 (node) + 512 (W_obj) + 32 (q) + 2048 (W_q) = 6688 blocks
// ---------------------------------------------------------------------------
__global__ __launch_bounds__(256)
void cvt_all_kernel(const float* __restrict__ nf, const float* __restrict__ wo,
                    const float* __restrict__ qf, const float* __restrict__ wq,
                    __nv_bfloat16* __restrict__ nodeB, __nv_bfloat16* __restrict__ wobjB,
                    __nv_bfloat16* __restrict__ qB, __nv_bfloat16* __restrict__ wqB)
{
    const int bid = blockIdx.x;
    const float* src; __nv_bfloat16* dst; int lb;
    if (bid < 4096)      { src = nf; dst = nodeB; lb = bid; }
    else if (bid < 4608) { src = wo; dst = wobjB; lb = bid - 4096; }
    else if (bid < 4640) { src = qf; dst = qB;    lb = bid - 4608; }
    else                 { src = wq; dst = wqB;   lb = bid - 4640; }
    const int i = lb * 256 + threadIdx.x;      // unit: 8 floats
    float4 v0 = ((const float4*)src)[i * 2];
    float4 v1 = ((const float4*)src)[i * 2 + 1];
    __nv_bfloat162 o0 = __floats2bfloat162_rn(v0.x, v0.y);
    __nv_bfloat162 o1 = __floats2bfloat162_rn(v0.z, v0.w);
    __nv_bfloat162 o2 = __floats2bfloat162_rn(v1.x, v1.y);
    __nv_bfloat162 o3 = __floats2bfloat162_rn(v1.z, v1.w);
    uint4 pack;
    pack.x = *(uint32_t*)&o0; pack.y = *(uint32_t*)&o1;
    pack.z = *(uint32_t*)&o2; pack.w = *(uint32_t*)&o3;
    ((uint4*)dst)[i] = pack;
}

// ---------------------------------------------------------------------------
// GEMM2: q_h[64,4096] = relu(q_feats @ W_q + b_q), fused norm partials.
// BM=64, BN=64, BK=64, 4 warps, 3-stage cp.async pipeline. grid = (64).
// ---------------------------------------------------------------------------
__global__ __launch_bounds__(128)
void gemm2_kernel(const __nv_bfloat16* __restrict__ A, const __nv_bfloat16* __restrict__ Bm,
                  const float* __restrict__ bias, float* __restrict__ C,
                  float* __restrict__ norm8)
{
    constexpr int BM = 64, BN = 64, BK = 64, S = 3;
    constexpr int AP = BK + 8, BP = BN + 8;
    constexpr int STA = BM * AP * 2, STB = BK * BP * 2;
    constexpr int ACH = BM * BK / 8, BCH = BK * BN / 8;
    constexpr int PT = (ACH + BCH) / 128;
    constexpr int NIT = QDIM / BK;
    constexpr int CP = BN + 4;

    extern __shared__ __align__(16) char smem[];
    const uint32_t sA = smem_u32(smem);
    const uint32_t sB = sA + S * STA;

    const int tid = threadIdx.x;
    const int wid = tid >> 5;
    const int wm = wid & 1, wn = wid >> 1;
    const int bN = blockIdx.x * BN;

    auto load_slab = [&](int slab) {
        const int s = slab % S, k0 = slab * BK;
#pragma unroll
        for (int t = 0; t < PT; t++) {
            int l = tid + t * 128;
            if (l < ACH) {
                int r = l >> 3, c = l & 7;
                cp_async16(sA + s * STA + (r * AP + c * 8) * 2,
                           A + (size_t)r * QDIM + k0 + c * 8);
            } else {
                int l2 = l - ACH;
                int r = l2 >> 3, c = l2 & 7;
                cp_async16(sB + s * STB + (r * BP + c * 8) * 2,
                           Bm + (size_t)(k0 + r) * HIDKS + bN + c * 8);
            }
        }
    };

    wmma::fragment<wmma::accumulator, 16, 16, 16, float> acc[2][2];
#pragma unroll
    for (int i = 0; i < 2; i++)
#pragma unroll
        for (int j = 0; j < 2; j++) wmma::fill_fragment(acc[i][j], 0.0f);

#pragma unroll
    for (int s = 0; s < S; s++) { load_slab(s); cp_commit(); }

    for (int i = 0; i < NIT; i++) {
        cp_wait<S - 2>();
        __syncthreads();
        if (i >= 1) {
            int j = i - 1 + S;
            if (j < NIT) load_slab(j);
            cp_commit();
        }
        const __nv_bfloat16* as = (const __nv_bfloat16*)(smem + (size_t)(i % S) * STA);
        const __nv_bfloat16* bs = (const __nv_bfloat16*)(smem + (size_t)S * STA + (size_t)(i % S) * STB);
#pragma unroll
        for (int kk = 0; kk < BK / 16; kk++) {
            wmma::fragment<wmma::matrix_a, 16, 16, 16, __nv_bfloat16, wmma::row_major> af[2];
            wmma::fragment<wmma::matrix_b, 16, 16, 16, __nv_bfloat16, wmma::row_major> bf[2];
#pragma unroll
            for (int f = 0; f < 2; f++)
                wmma::load_matrix_sync(af[f], as + (wm * 32 + f * 16) * AP + kk * 16, AP);
#pragma unroll
            for (int j = 0; j < 2; j++)
                wmma::load_matrix_sync(bf[j], bs + (kk * 16) * BP + wn * 32 + j * 16, BP);
#pragma unroll
            for (int f = 0; f < 2; f++)
#pragma unroll
                for (int j = 0; j < 2; j++)
                    wmma::mma_sync(acc[f][j], af[f], bf[j], acc[f][j]);
        }
    }

    __syncthreads();
    float* Cs = (float*)smem;
    float* biasS = Cs + BM * CP;
#pragma unroll
    for (int f = 0; f < 2; f++)
#pragma unroll
        for (int j = 0; j < 2; j++)
            wmma::store_matrix_sync(Cs + (wm * 32 + f * 16) * CP + wn * 32 + j * 16,
                                    acc[f][j], CP, wmma::mem_row_major);
    if (tid < BN) biasS[tid] = bias[bN + tid];
    __syncthreads();

#pragma unroll
    for (int t = 0; t < (BM * BN / 4) / 128; t++) {
        int l = tid + t * 128;
        int r = l >> 4, c4 = (l & 15) * 4;
        float4 v = *(float4*)(Cs + r * CP + c4);
        v.x = fmaxf(v.x + biasS[c4 + 0], 0.0f);
        v.y = fmaxf(v.y + biasS[c4 + 1], 0.0f);
        v.z = fmaxf(v.z + biasS[c4 + 2], 0.0f);
        v.w = fmaxf(v.w + biasS[c4 + 3], 0.0f);
        *(float4*)(C + (size_t)r * HIDKS + bN + c4) = v;
    }
    if (tid < BM) {
        float a[KS];
#pragma unroll
        for (int k = 0; k < KS; k++) a[k] = 0.0f;
#pragma unroll
        for (int c0 = 0; c0 < 8; c0++)
#pragma unroll
            for (int j = 0; j < 8; j++) {
                float v = fmaxf(Cs[tid * CP + c0 * 8 + j] + biasS[c0 * 8 + j], 0.0f);
                a[j] += v * v;
            }
        float* dst = norm8 + (size_t)blockIdx.x * (B_IMG * KS) + tid * KS;
        *(float4*)dst       = make_float4(a[0], a[1], a[2], a[3]);
        *(float4*)(dst + 4) = make_float4(a[4], a[5], a[6], a[7]);
    }
}

// ---------------------------------------------------------------------------
// GEMM1 fused with P contraction. BM=128, BN=64, BK=64, 4 warps (128 thr),
// warp tile 64x32: FM=4, FN=2 (8 mma per 6 frag loads, 8 acc frags of ILP).
// grid = (8, 32); smem 83 KB -> 2 CTAs/SM.
// ---------------------------------------------------------------------------
__global__ __launch_bounds__(128)
void gemm1_kernel(const __nv_bfloat16* __restrict__ A, const __nv_bfloat16* __restrict__ Bm,
                  const float* __restrict__ bias, const float* __restrict__ qh,
                  float* __restrict__ P8)
{
    constexpr int BM = 128, BN = 64, BK = 64, S = 3;
    constexpr int FM = 4, FN = 2;
    constexpr int AP = BK + 8, BP = BN + 8;
    constexpr int STA = BM * AP * 2, STB = BK * BP * 2;    // 18432, 9216
    constexpr int ACH = BM * BK / 8, BCH = BK * BN / 8;    // 1024, 512
    constexpr int PT = (ACH + BCH) / 128;                  // 12
    constexpr int NIT = OBJDIM / BK;                       // 32
    constexpr int CP = BN + 4;                             // 68

    extern __shared__ __align__(16) char smem[];
    const uint32_t sA = smem_u32(smem);
    const uint32_t sB = sA + S * STA;

    const int tid = threadIdx.x;
    const int wid = tid >> 5;
    const int wm = wid & 1, wn = wid >> 1;                 // 2 x 2 warps
    const int bM = blockIdx.y * BM;
    const int bN = blockIdx.x * BN;

    auto load_slab = [&](int slab) {
        const int s = slab % S, k0 = slab * BK;
#pragma unroll
        for (int t = 0; t < PT; t++) {
            int l = tid + t * 128;
            if (l < ACH) {
                int r = l >> 3, c = l & 7;
                cp_async16(sA + s * STA + (r * AP + c * 8) * 2,
                           A + (size_t)(bM + r) * OBJDIM + k0 + c * 8);
            } else {
                int l2 = l - ACH;
                int r = l2 >> 3, c = l2 & 7;
                cp_async16(sB + s * STB + (r * BP + c * 8) * 2,
                           Bm + (size_t)(k0 + r) * HID + bN + c * 8);
            }
        }
    };

    wmma::fragment<wmma::accumulator, 16, 16, 16, float> acc[FM][FN];
#pragma unroll
    for (int i = 0; i < FM; i++)
#pragma unroll
        for (int j = 0; j < FN; j++) wmma::fill_fragment(acc[i][j], 0.0f);

#pragma unroll
    for (int s = 0; s < S; s++) { load_slab(s); cp_commit(); }

    for (int i = 0; i < NIT; i++) {
        cp_wait<S - 2>();
        __syncthreads();
        if (i >= 1) {
            int j = i - 1 + S;
            if (j < NIT) load_slab(j);
            cp_commit();
        }
        const __nv_bfloat16* as = (const __nv_bfloat16*)(smem + (size_t)(i % S) * STA);
        const __nv_bfloat16* bs = (const __nv_bfloat16*)(smem + (size_t)S * STA + (size_t)(i % S) * STB);
#pragma unroll
        for (int kk = 0; kk < BK / 16; kk++) {
            wmma::fragment<wmma::matrix_a, 16, 16, 16, __nv_bfloat16, wmma::row_major> af[FM];
            wmma::fragment<wmma::matrix_b, 16, 16, 16, __nv_bfloat16, wmma::row_major> bf[FN];
#pragma unroll
            for (int f = 0; f < FM; f++)
                wmma::load_matrix_sync(af[f], as + (wm * 64 + f * 16) * AP + kk * 16, AP);
#pragma unroll
            for (int j = 0; j < FN; j++)
                wmma::load_matrix_sync(bf[j], bs + (kk * 16) * BP + wn * 32 + j * 16, BP);
#pragma unroll
            for (int f = 0; f < FM; f++)
#pragma unroll
                for (int j = 0; j < FN; j++)
                    wmma::mma_sync(acc[f][j], af[f], bf[j], acc[f][j]);
        }
    }

    // Epilogue: C tile -> smem, then contract vs q_h into P8 (exclusive writes)
    __syncthreads();
    float* Cs    = (float*)smem;                 // 128 x 68 = 34816 B
    float* qs    = Cs + BM * CP;                 // 2 x 512 floats
    float* biasS = qs + 2 * 512;                 // 64 floats
#pragma unroll
    for (int f = 0; f < FM; f++)
#pragma unroll
        for (int j = 0; j < FN; j++)
            wmma::store_matrix_sync(Cs + (wm * 64 + f * 16) * CP + wn * 32 + j * 16,
                                    acc[f][j], CP, wmma::mem_row_major);
    {   // stage q_h segments for the two batches covered by this M-tile
        const int bB0 = bM >> 6;
#pragma unroll
        for (int t = 0; t < 2; t++) {
            int idx = tid + t * 128;             // 256 float4 slots
            int s = idx >> 7, i4 = (idx & 127) * 4;
            *(float4*)(qs + s * 512 + i4) =
                *(const float4*)(qh + (size_t)(bB0 + s) * HIDKS + bN * KS + i4);
        }
        if (tid < BN) biasS[tid] = bias[bN + tid];
    }
    __syncthreads();

    // one thread per row: acc over all 64 columns, all 8 k
    const int r = tid;
    const float* qsp = qs + (r >> 6) * 512;
    float a[KS];
#pragma unroll
    for (int k = 0; k < KS; k++) a[k] = 0.0f;
#pragma unroll 8
    for (int c = 0; c < BN; c++) {
        float v = fmaxf(Cs[r * CP + c] + biasS[c], 0.0f);
        float4 q0 = *(const float4*)(qsp + c * 8);
        float4 q1 = *(const float4*)(qsp + c * 8 + 4);
        a[0] += v * q0.x; a[1] += v * q0.y; a[2] += v * q0.z; a[3] += v * q0.w;
        a[4] += v * q1.x; a[5] += v * q1.y; a[6] += v * q1.z; a[7] += v * q1.w;
    }
    float* dst = P8 + (size_t)blockIdx.x * (4096 * KS) + (size_t)(bM + r) * KS;
    *(float4*)dst       = make_float4(a[0], a[1], a[2], a[3]);
    *(float4*)(dst + 4) = make_float4(a[4], a[5], a[6], a[7]);
}

// ---------------------------------------------------------------------------
// Finalize (vectorized): P = sum_nt P8[nt] (float4), inv = rsqrt(sum norm8)
// grid = 34 blocks: 32 for P (8192 float4), 2 for inv (512 floats)
// ---------------------------------------------------------------------------
__global__ __launch_bounds__(256)
void finalize_kernel(const float* __restrict__ P8, float* __restrict__ P,
                     const float* __restrict__ norm8, float* __restrict__ inv)
{
    const int gid = blockIdx.x * 256 + threadIdx.x;
    if (gid < 8192) {                            // float4 units of P
        const float4* src = (const float4*)P8;
        float4 s = make_float4(0.f, 0.f, 0.f, 0.f);
#pragma unroll
        for (int nt = 0; nt < 8; nt++) {
            float4 v = src[nt * 8192 + gid];
            s.x += v.x; s.y += v.y; s.z += v.z; s.w += v.w;
        }
        ((float4*)P)[gid] = s;
    } else if (gid < 8192 + B_IMG * KS) {
        const int i = gid - 8192;
        float s = 0.f;
#pragma unroll
        for (int nt = 0; nt < 64; nt++) s += norm8[nt * (B_IMG * KS) + i];
        inv[i] = rsqrtf(s);
    }
}

// ---------------------------------------------------------------------------
// out[m, k] = (P[b,src,k] + P[b,dst,k]) * inv[b,k]
// ---------------------------------------------------------------------------
__global__ __launch_bounds__(256)
void gather_kernel(const int* __restrict__ idxs, const float* __restrict__ P,
                   const float* __restrict__ inv, float* __restrict__ out)
{
    const int m = blockIdx.x * 256 + threadIdx.x;
    const int idx = __ldg(idxs + m);
    const int b = idx >> 12, rem = idx & 4095;
    const int src = rem >> 6, dst = rem & 63;
    const float4* ps = (const float4*)(P + (size_t)(b * N_OBJ + src) * KS);
    const float4* pd = (const float4*)(P + (size_t)(b * N_OBJ + dst) * KS);
    const float4* iv = (const float4*)(inv + b * KS);
    float4 s0 = ps[0], s1 = ps[1], d0 = pd[0], d1 = pd[1], i0 = iv[0], i1 = iv[1];
    float4 o0 = make_float4((s0.x + d0.x) * i0.x, (s0.y + d0.y) * i0.y,
                            (s0.z + d0.z) * i0.z, (s0.w + d0.w) * i0.w);
    float4 o1 = make_float4((s1.x + d1.x) * i1.x, (s1.y + d1.y) * i1.y,
                            (s1.z + d1.z) * i1.z, (s1.w + d1.w) * i1.w);
    ((float4*)out)[(size_t)m * 2]     = o0;
    ((float4*)out)[(size_t)m * 2 + 1] = o1;
}

// ---------------------------------------------------------------------------
extern "C" void kernel_launch(void* const* d_in, const int* in_sizes, int n_in,
                              void* d_out, int out_size)
{
    const float* node_feats = (const float*)d_in[0];
    const float* q_feats    = (const float*)d_in[1];
    const int*   indexes    = (const int*)d_in[2];
    const float* W_obj      = (const float*)d_in[3];
    const float* b_obj      = (const float*)d_in[4];
    const float* W_q        = (const float*)d_in[5];
    const float* b_q        = (const float*)d_in[6];
    float* out = (float*)d_out;

    __nv_bfloat16 *nodeB, *wobjB, *qB, *wqB;
    float *qh, *P8, *P, *norm8, *inv;
    cudaGetSymbolAddress((void**)&nodeB, g_nodeB);
    cudaGetSymbolAddress((void**)&wobjB, g_WobjB);
    cudaGetSymbolAddress((void**)&qB,    g_qB);
    cudaGetSymbolAddress((void**)&wqB,   g_WqB);
    cudaGetSymbolAddress((void**)&qh,    g_q_h);
    cudaGetSymbolAddress((void**)&P8,    g_P8);
    cudaGetSymbolAddress((void**)&P,     g_P);
    cudaGetSymbolAddress((void**)&norm8, g_norm8);
    cudaGetSymbolAddress((void**)&inv,   g_inv);

    // 1) all fp32 -> bf16 conversions, one launch
    cvt_all_kernel<<<6688, 256>>>(node_feats, W_obj, q_feats, W_q,
                                  nodeB, wobjB, qB, wqB);

    // 2) GEMM2 + norm partials (must precede GEMM1: epilogue consumes q_h)
    {
        constexpr int SM = 3 * (64 * 72 * 2 + 64 * 72 * 2);
        cudaFuncSetAttribute(gemm2_kernel, cudaFuncAttributeMaxDynamicSharedMemorySize, SM);
        gemm2_kernel<<<dim3(HIDKS / 64, 1), 128, SM>>>(qB, wqB, b_q, qh, norm8);
    }
    // 3) GEMM1 fused with P contraction
    {
        constexpr int SM = 3 * (128 * 72 * 2 + 64 * 72 * 2);
        cudaFuncSetAttribute(gemm1_kernel, cudaFuncAttributeMaxDynamicSharedMemorySize, SM);
        gemm1_kernel<<<dim3(HID / 64, 4096 / 128), 128, SM>>>(nodeB, wobjB, b_obj, qh, P8);
    }
    // 4) reduce partials (vectorized)
    finalize_kernel<<<34, 256>>>(P8, P, norm8, inv);
    // 5) edge gather
    gather_kernel<<<M_EDGE / 256, 256>>>(indexes, P, inv, out);
}

// round 8
// speedup vs baseline: 3.2402x; 1.0606x over previous
#include <cuda_runtime.h>
#include <cuda_bf16.h>
#include <mma.h>
#include <cstdint>

using namespace nvcuda;

// Problem constants
#define B_IMG   64
#define N_OBJ   64
#define M_EDGE  32768
#define OBJDIM  2048
#define QDIM    1024
#define KS      8
#define HID     512
#define HIDKS   4096
#define N2TILES 128                              // GEMM2 N-tiles (width 32)

// Scratch (device globals; no cudaMalloc allowed)
__device__ __nv_bfloat16 g_nodeB[(size_t)4096 * OBJDIM];
__device__ __nv_bfloat16 g_WobjB[(size_t)OBJDIM * HID];
__device__ __nv_bfloat16 g_qB[(size_t)B_IMG * QDIM];
__device__ __nv_bfloat16 g_WqB[(size_t)QDIM * HIDKS];
__device__ float g_q_h[(size_t)B_IMG * HIDKS];           // [64, 4096]
__device__ float g_P8[(size_t)8 * 4096 * KS];            // per-Ntile P partials
__device__ float g_norm8[(size_t)N2TILES * B_IMG * KS];  // per-Ntile norm partials
__device__ float g_inv[B_IMG * KS];

// ---------------------------------------------------------------------------
__device__ __forceinline__ uint32_t smem_u32(const void* p) {
    uint32_t a;
    asm("{ .reg .u64 t; cvta.to.shared.u64 t, %1; cvt.u32.u64 %0, t; }" : "=r"(a) : "l"(p));
    return a;
}
__device__ __forceinline__ void cp_async16(uint32_t dst, const void* src) {
    asm volatile("cp.async.cg.shared.global [%0], [%1], 16;\n" :: "r"(dst), "l"(src));
}
__device__ __forceinline__ void cp_commit() { asm volatile("cp.async.commit_group;\n"); }
template<int N> __device__ __forceinline__ void cp_wait() {
    asm volatile("cp.async.wait_group %0;\n" :: "n"(N));
}

// ---------------------------------------------------------------------------
// Fused fp32 -> bf16 conversion, 32B read / 16B write per thread.
// grid = 4096 (node) + 512 (W_obj) + 32 (q) + 2048 (W_q) = 6688 blocks
// ---------------------------------------------------------------------------
__global__ __launch_bounds__(256)
void cvt_all_kernel(const float* __restrict__ nf, const float* __restrict__ wo,
                    const float* __restrict__ qf, const float* __restrict__ wq,
                    __nv_bfloat16* __restrict__ nodeB, __nv_bfloat16* __restrict__ wobjB,
                    __nv_bfloat16* __restrict__ qB, __nv_bfloat16* __restrict__ wqB)
{
    const int bid = blockIdx.x;
    const float* src; __nv_bfloat16* dst; int lb;
    if (bid < 4096)      { src = nf; dst = nodeB; lb = bid; }
    else if (bid < 4608) { src = wo; dst = wobjB; lb = bid - 4096; }
    else if (bid < 4640) { src = qf; dst = qB;    lb = bid - 4608; }
    else                 { src = wq; dst = wqB;   lb = bid - 4640; }
    const int i = lb * 256 + threadIdx.x;      // unit: 8 floats
    float4 v0 = ((const float4*)src)[i * 2];
    float4 v1 = ((const float4*)src)[i * 2 + 1];
    __nv_bfloat162 o0 = __floats2bfloat162_rn(v0.x, v0.y);
    __nv_bfloat162 o1 = __floats2bfloat162_rn(v0.z, v0.w);
    __nv_bfloat162 o2 = __floats2bfloat162_rn(v1.x, v1.y);
    __nv_bfloat162 o3 = __floats2bfloat162_rn(v1.z, v1.w);
    uint4 pack;
    pack.x = *(uint32_t*)&o0; pack.y = *(uint32_t*)&o1;
    pack.z = *(uint32_t*)&o2; pack.w = *(uint32_t*)&o3;
    ((uint4*)dst)[i] = pack;
}

// ---------------------------------------------------------------------------
// GEMM2: q_h[64,4096] = relu(q_feats @ W_q + b_q), fused norm partials.
// BM=64, BN=32, BK=64, 4 warps (warp tile 32x16), 3-stage pipeline.
// grid = (128): better SM coverage than 64 wide tiles.
// ---------------------------------------------------------------------------
__global__ __launch_bounds__(128)
void gemm2_kernel(const __nv_bfloat16* __restrict__ A, const __nv_bfloat16* __restrict__ Bm,
                  const float* __restrict__ bias, float* __restrict__ C,
                  float* __restrict__ norm8)
{
    constexpr int BM = 64, BN = 32, BK = 64, S = 3;
    constexpr int AP = BK + 8, BP = BN + 8;
    constexpr int STA = BM * AP * 2, STB = BK * BP * 2;    // 9216, 5120
    constexpr int ACH = BM * BK / 8, BCH = BK * BN / 8;    // 512, 256
    constexpr int PT = (ACH + BCH) / 128;                  // 6
    constexpr int NIT = QDIM / BK;                         // 16
    constexpr int CP = BN + 4;                             // 36

    extern __shared__ __align__(16) char smem[];
    const uint32_t sA = smem_u32(smem);
    const uint32_t sB = sA + S * STA;

    const int tid = threadIdx.x;
    const int wid = tid >> 5;
    const int wm = wid & 1, wn = wid >> 1;                 // 2 x 2 warps
    const int bN = blockIdx.x * BN;

    auto load_slab = [&](int slab) {
        const int s = slab % S, k0 = slab * BK;
#pragma unroll
        for (int t = 0; t < PT; t++) {
            int l = tid + t * 128;
            if (l < ACH) {
                int r = l >> 3, c = l & 7;
                cp_async16(sA + s * STA + (r * AP + c * 8) * 2,
                           A + (size_t)r * QDIM + k0 + c * 8);
            } else {
                int l2 = l - ACH;
                int r = l2 >> 2, c = l2 & 3;
                cp_async16(sB + s * STB + (r * BP + c * 8) * 2,
                           Bm + (size_t)(k0 + r) * HIDKS + bN + c * 8);
            }
        }
    };

    wmma::fragment<wmma::accumulator, 16, 16, 16, float> acc[2];
#pragma unroll
    for (int f = 0; f < 2; f++) wmma::fill_fragment(acc[f], 0.0f);

#pragma unroll
    for (int s = 0; s < S; s++) { load_slab(s); cp_commit(); }

    for (int i = 0; i < NIT; i++) {
        cp_wait<S - 2>();
        __syncthreads();
        if (i >= 1) {
            int j = i - 1 + S;
            if (j < NIT) load_slab(j);
            cp_commit();
        }
        const __nv_bfloat16* as = (const __nv_bfloat16*)(smem + (size_t)(i % S) * STA);
        const __nv_bfloat16* bs = (const __nv_bfloat16*)(smem + (size_t)S * STA + (size_t)(i % S) * STB);
#pragma unroll
        for (int kk = 0; kk < BK / 16; kk++) {
            wmma::fragment<wmma::matrix_a, 16, 16, 16, __nv_bfloat16, wmma::row_major> af[2];
            wmma::fragment<wmma::matrix_b, 16, 16, 16, __nv_bfloat16, wmma::row_major> bf;
#pragma unroll
            for (int f = 0; f < 2; f++)
                wmma::load_matrix_sync(af[f], as + (wm * 32 + f * 16) * AP + kk * 16, AP);
            wmma::load_matrix_sync(bf, bs + (kk * 16) * BP + wn * 16, BP);
#pragma unroll
            for (int f = 0; f < 2; f++)
                wmma::mma_sync(acc[f], af[f], bf, acc[f]);
        }
    }

    __syncthreads();
    float* Cs = (float*)smem;                    // 64 x 36 floats
    float* biasS = Cs + BM * CP;                 // 32 floats
#pragma unroll
    for (int f = 0; f < 2; f++)
        wmma::store_matrix_sync(Cs + (wm * 32 + f * 16) * CP + wn * 16,
                                acc[f], CP, wmma::mem_row_major);
    if (tid < BN) biasS[tid] = bias[bN + tid];
    __syncthreads();

    // q_h writes: 64 rows x 32 cols = 512 float4
#pragma unroll
    for (int t = 0; t < 4; t++) {
        int l = tid + t * 128;
        int r = l >> 3, c4 = (l & 7) * 4;
        float4 v = *(float4*)(Cs + r * CP + c4);
        v.x = fmaxf(v.x + biasS[c4 + 0], 0.0f);
        v.y = fmaxf(v.y + biasS[c4 + 1], 0.0f);
        v.z = fmaxf(v.z + biasS[c4 + 2], 0.0f);
        v.w = fmaxf(v.w + biasS[c4 + 3], 0.0f);
        *(float4*)(C + (size_t)r * HIDKS + bN + c4) = v;
    }
    // Norm partials: one thread per batch row; col c -> k = c & 7
    if (tid < BM) {
        float a[KS];
#pragma unroll
        for (int k = 0; k < KS; k++) a[k] = 0.0f;
#pragma unroll
        for (int c = 0; c < BN; c++) {
            float v = fmaxf(Cs[tid * CP + c] + biasS[c], 0.0f);
            a[c & 7] += v * v;
        }
        float* dst = norm8 + (size_t)blockIdx.x * (B_IMG * KS) + tid * KS;
        *(float4*)dst       = make_float4(a[0], a[1], a[2], a[3]);
        *(float4*)(dst + 4) = make_float4(a[4], a[5], a[6], a[7]);
    }
}

// ---------------------------------------------------------------------------
// GEMM1 fused with P contraction. BM=128, BN=64, BK=64, 4 warps (128 thr),
// warp tile 64x32: FM=4, FN=2. grid = (8, 32); smem 83 KB -> 2 CTAs/SM.
// ---------------------------------------------------------------------------
__global__ __launch_bounds__(128)
void gemm1_kernel(const __nv_bfloat16* __restrict__ A, const __nv_bfloat16* __restrict__ Bm,
                  const float* __restrict__ bias, const float* __restrict__ qh,
                  float* __restrict__ P8)
{
    constexpr int BM = 128, BN = 64, BK = 64, S = 3;
    constexpr int FM = 4, FN = 2;
    constexpr int AP = BK + 8, BP = BN + 8;
    constexpr int STA = BM * AP * 2, STB = BK * BP * 2;    // 18432, 9216
    constexpr int ACH = BM * BK / 8, BCH = BK * BN / 8;    // 1024, 512
    constexpr int PT = (ACH + BCH) / 128;                  // 12
    constexpr int NIT = OBJDIM / BK;                       // 32
    constexpr int CP = BN + 4;                             // 68

    extern __shared__ __align__(16) char smem[];
    const uint32_t sA = smem_u32(smem);
    const uint32_t sB = sA + S * STA;

    const int tid = threadIdx.x;
    const int wid = tid >> 5;
    const int wm = wid & 1, wn = wid >> 1;                 // 2 x 2 warps
    const int bM = blockIdx.y * BM;
    const int bN = blockIdx.x * BN;

    auto load_slab = [&](int slab) {
        const int s = slab % S, k0 = slab * BK;
#pragma unroll
        for (int t = 0; t < PT; t++) {
            int l = tid + t * 128;
            if (l < ACH) {
                int r = l >> 3, c = l & 7;
                cp_async16(sA + s * STA + (r * AP + c * 8) * 2,
                           A + (size_t)(bM + r) * OBJDIM + k0 + c * 8);
            } else {
                int l2 = l - ACH;
                int r = l2 >> 3, c = l2 & 7;
                cp_async16(sB + s * STB + (r * BP + c * 8) * 2,
                           Bm + (size_t)(k0 + r) * HID + bN + c * 8);
            }
        }
    };

    wmma::fragment<wmma::accumulator, 16, 16, 16, float> acc[FM][FN];
#pragma unroll
    for (int i = 0; i < FM; i++)
#pragma unroll
        for (int j = 0; j < FN; j++) wmma::fill_fragment(acc[i][j], 0.0f);

#pragma unroll
    for (int s = 0; s < S; s++) { load_slab(s); cp_commit(); }

    for (int i = 0; i < NIT; i++) {
        cp_wait<S - 2>();
        __syncthreads();
        if (i >= 1) {
            int j = i - 1 + S;
            if (j < NIT) load_slab(j);
            cp_commit();
        }
        const __nv_bfloat16* as = (const __nv_bfloat16*)(smem + (size_t)(i % S) * STA);
        const __nv_bfloat16* bs = (const __nv_bfloat16*)(smem + (size_t)S * STA + (size_t)(i % S) * STB);
#pragma unroll
        for (int kk = 0; kk < BK / 16; kk++) {
            wmma::fragment<wmma::matrix_a, 16, 16, 16, __nv_bfloat16, wmma::row_major> af[FM];
            wmma::fragment<wmma::matrix_b, 16, 16, 16, __nv_bfloat16, wmma::row_major> bf[FN];
#pragma unroll
            for (int f = 0; f < FM; f++)
                wmma::load_matrix_sync(af[f], as + (wm * 64 + f * 16) * AP + kk * 16, AP);
#pragma unroll
            for (int j = 0; j < FN; j++)
                wmma::load_matrix_sync(bf[j], bs + (kk * 16) * BP + wn * 32 + j * 16, BP);
#pragma unroll
            for (int f = 0; f < FM; f++)
#pragma unroll
                for (int j = 0; j < FN; j++)
                    wmma::mma_sync(acc[f][j], af[f], bf[j], acc[f][j]);
        }
    }

    // Epilogue: C tile -> smem, then contract vs q_h into P8 (exclusive writes)
    __syncthreads();
    float* Cs    = (float*)smem;                 // 128 x 68 = 34816 B
    float* qs    = Cs + BM * CP;                 // 2 x 512 floats
    float* biasS = qs + 2 * 512;                 // 64 floats
#pragma unroll
    for (int f = 0; f < FM; f++)
#pragma unroll
        for (int j = 0; j < FN; j++)
            wmma::store_matrix_sync(Cs + (wm * 64 + f * 16) * CP + wn * 32 + j * 16,
                                    acc[f][j], CP, wmma::mem_row_major);
    {   // stage q_h segments for the two batches covered by this M-tile
        const int bB0 = bM >> 6;
#pragma unroll
        for (int t = 0; t < 2; t++) {
            int idx = tid + t * 128;             // 256 float4 slots
            int s = idx >> 7, i4 = (idx & 127) * 4;
            *(float4*)(qs + s * 512 + i4) =
                *(const float4*)(qh + (size_t)(bB0 + s) * HIDKS + bN * KS + i4);
        }
        if (tid < BN) biasS[tid] = bias[bN + tid];
    }
    __syncthreads();

    // one thread per row: acc over all 64 columns, all 8 k
    const int r = tid;
    const float* qsp = qs + (r >> 6) * 512;
    float a[KS];
#pragma unroll
    for (int k = 0; k < KS; k++) a[k] = 0.0f;
#pragma unroll 8
    for (int c = 0; c < BN; c++) {
        float v = fmaxf(Cs[r * CP + c] + biasS[c], 0.0f);
        float4 q0 = *(const float4*)(qsp + c * 8);
        float4 q1 = *(const float4*)(qsp + c * 8 + 4);
        a[0] += v * q0.x; a[1] += v * q0.y; a[2] += v * q0.z; a[3] += v * q0.w;
        a[4] += v * q1.x; a[5] += v * q1.y; a[6] += v * q1.z; a[7] += v * q1.w;
    }
    float* dst = P8 + (size_t)blockIdx.x * (4096 * KS) + (size_t)(bM + r) * KS;
    *(float4*)dst       = make_float4(a[0], a[1], a[2], a[3]);
    *(float4*)(dst + 4) = make_float4(a[4], a[5], a[6], a[7]);
}

// ---------------------------------------------------------------------------
// Fused finalize + gather: one block per batch (64 blocks, 256 threads).
// Stage 1: reduce P8 (8 ntiles) for this batch's 64 rows into smem;
//          reduce norm8 (128 ntiles) into inv in smem.
// Stage 2: emit this batch's 512 edges from smem.
// ---------------------------------------------------------------------------
__global__ __launch_bounds__(256)
void finalize_gather_kernel(const int* __restrict__ idxs, const float* __restrict__ P8,
                            const float* __restrict__ norm8, float* __restrict__ out)
{
    __shared__ float Ps[N_OBJ * KS];             // 512 floats
    __shared__ float normS[KS * 16];
    __shared__ float invS[KS];
    const int b   = blockIdx.x;
    const int tid = threadIdx.x;

    if (tid < 128) {
        // each thread one float4 of P: row = tid>>1, half = tid&1
        const float4* src = (const float4*)P8;
        const int base = b * N_OBJ * 2;          // float4 index of row 0
        float4 s = make_float4(0.f, 0.f, 0.f, 0.f);
#pragma unroll
        for (int nt = 0; nt < 8; nt++) {
            float4 v = src[nt * 8192 + base + tid];
            s.x += v.x; s.y += v.y; s.z += v.z; s.w += v.w;
        }
        ((float4*)Ps)[tid] = s;
    } else {
        // 128 threads: (k, part) with part summing 8 of the 128 norm tiles
        const int t = tid - 128;
        const int k = t & 7, part = t >> 3;      // part in [0,16)
        float s = 0.f;
#pragma unroll
        for (int i = 0; i < 8; i++) {
            int nt = part * 8 + i;
            s += norm8[(size_t)nt * (B_IMG * KS) + b * KS + k];
        }
        normS[k * 16 + part] = s;
    }
    __syncthreads();
    if (tid < KS) {
        float s = 0.f;
#pragma unroll
        for (int p = 0; p < 16; p++) s += normS[tid * 16 + p];
        invS[tid] = rsqrtf(s);
    }
    __syncthreads();

    const float4 i0 = *(const float4*)invS;
    const float4 i1 = *(const float4*)(invS + 4);
#pragma unroll
    for (int e = 0; e < 2; e++) {
        const int m = b * 512 + tid + e * 256;
        const int idx = __ldg(idxs + m);
        const int rem = idx & 4095;
        const int src = rem >> 6, dst = rem & 63;
        const float4* ps = (const float4*)(Ps + src * KS);
        const float4* pd = (const float4*)(Ps + dst * KS);
        float4 s0 = ps[0], s1 = ps[1], d0 = pd[0], d1 = pd[1];
        float4 o0 = make_float4((s0.x + d0.x) * i0.x, (s0.y + d0.y) * i0.y,
                                (s0.z + d0.z) * i0.z, (s0.w + d0.w) * i0.w);
        float4 o1 = make_float4((s1.x + d1.x) * i1.x, (s1.y + d1.y) * i1.y,
                                (s1.z + d1.z) * i1.z, (s1.w + d1.w) * i1.w);
        ((float4*)out)[(size_t)m * 2]     = o0;
        ((float4*)out)[(size_t)m * 2 + 1] = o1;
    }
}

// ---------------------------------------------------------------------------
extern "C" void kernel_launch(void* const* d_in, const int* in_sizes, int n_in,
                              void* d_out, int out_size)
{
    const float* node_feats = (const float*)d_in[0];
    const float* q_feats    = (const float*)d_in[1];
    const int*   indexes    = (const int*)d_in[2];
    const float* W_obj      = (const float*)d_in[3];
    const float* b_obj      = (const float*)d_in[4];
    const float* W_q        = (const float*)d_in[5];
    const float* b_q        = (const float*)d_in[6];
    float* out = (float*)d_out;

    __nv_bfloat16 *nodeB, *wobjB, *qB, *wqB;
    float *qh, *P8, *norm8;
    cudaGetSymbolAddress((void**)&nodeB, g_nodeB);
    cudaGetSymbolAddress((void**)&wobjB, g_WobjB);
    cudaGetSymbolAddress((void**)&qB,    g_qB);
    cudaGetSymbolAddress((void**)&wqB,   g_WqB);
    cudaGetSymbolAddress((void**)&qh,    g_q_h);
    cudaGetSymbolAddress((void**)&P8,    g_P8);
    cudaGetSymbolAddress((void**)&norm8, g_norm8);

    // 1) all fp32 -> bf16 conversions, one launch
    cvt_all_kernel<<<6688, 256>>>(node_feats, W_obj, q_feats, W_q,
                                  nodeB, wobjB, qB, wqB);

    // 2) GEMM2 + norm partials (must precede GEMM1: epilogue consumes q_h)
    {
        constexpr int SM = 3 * (64 * 72 * 2 + 64 * 40 * 2);      // 43008
        cudaFuncSetAttribute(gemm2_kernel, cudaFuncAttributeMaxDynamicSharedMemorySize, SM);
        gemm2_kernel<<<N2TILES, 128, SM>>>(qB, wqB, b_q, qh, norm8);
    }
    // 3) GEMM1 fused with P contraction
    {
        constexpr int SM = 3 * (128 * 72 * 2 + 64 * 72 * 2);     // 82944
        cudaFuncSetAttribute(gemm1_kernel, cudaFuncAttributeMaxDynamicSharedMemorySize, SM);
        gemm1_kernel<<<dim3(HID / 64, 4096 / 128), 128, SM>>>(nodeB, wobjB, b_obj, qh, P8);
    }
    // 4) fused finalize + edge gather (one block per batch)
    finalize_gather_kernel<<<B_IMG, 256>>>(indexes, P8, norm8, out);
}

// round 9
// speedup vs baseline: 3.6509x; 1.1268x over previous
#include <cuda_runtime.h>
#include <cuda_bf16.h>
#include <mma.h>
#include <cstdint>

using namespace nvcuda;

// Problem constants
#define B_IMG   64
#define N_OBJ   64
#define M_EDGE  32768
#define OBJDIM  2048
#define QDIM    1024
#define KS      8
#define HID     512
#define HIDKS   4096
#define N2TILES 128                              // GEMM2 N-tiles (width 32)

// Scratch (device globals; no cudaMalloc allowed)
__device__ __nv_bfloat16 g_nodeB[(size_t)4096 * OBJDIM];
__device__ __nv_bfloat16 g_WobjB[(size_t)OBJDIM * HID];
__device__ __nv_bfloat16 g_qB[(size_t)B_IMG * QDIM];
__device__ __nv_bfloat16 g_WqB[(size_t)QDIM * HIDKS];
__device__ float g_q_h[(size_t)B_IMG * HIDKS];           // [64, 4096]
__device__ float g_P8[(size_t)8 * 4096 * KS];            // per-Ntile P partials
__device__ float g_norm8[(size_t)B_IMG * KS * N2TILES];  // [b][k][ntile]

// ---------------------------------------------------------------------------
__device__ __forceinline__ uint32_t smem_u32(const void* p) {
    uint32_t a;
    asm("{ .reg .u64 t; cvta.to.shared.u64 t, %1; cvt.u32.u64 %0, t; }" : "=r"(a) : "l"(p));
    return a;
}
__device__ __forceinline__ void cp_async16(uint32_t dst, const void* src) {
    asm volatile("cp.async.cg.shared.global [%0], [%1], 16;\n" :: "r"(dst), "l"(src));
}
__device__ __forceinline__ void cp_commit() { asm volatile("cp.async.commit_group;\n"); }
template<int N> __device__ __forceinline__ void cp_wait() {
    asm volatile("cp.async.wait_group %0;\n" :: "n"(N));
}
__device__ __forceinline__ void ldsm_x4(uint32_t& r0, uint32_t& r1, uint32_t& r2,
                                        uint32_t& r3, uint32_t addr) {
    asm volatile("ldmatrix.sync.aligned.m8n8.x4.shared.b16 {%0,%1,%2,%3}, [%4];"
        : "=r"(r0), "=r"(r1), "=r"(r2), "=r"(r3) : "r"(addr));
}
__device__ __forceinline__ void ldsm_x4_t(uint32_t& r0, uint32_t& r1, uint32_t& r2,
                                          uint32_t& r3, uint32_t addr) {
    asm volatile("ldmatrix.sync.aligned.m8n8.x4.trans.shared.b16 {%0,%1,%2,%3}, [%4];"
        : "=r"(r0), "=r"(r1), "=r"(r2), "=r"(r3) : "r"(addr));
}
__device__ __forceinline__ void mma_bf16(float* d, const uint32_t* a,
                                         uint32_t b0, uint32_t b1) {
    asm volatile("mma.sync.aligned.m16n8k16.row.col.f32.bf16.bf16.f32 "
        "{%0,%1,%2,%3}, {%4,%5,%6,%7}, {%8,%9}, {%0,%1,%2,%3};"
        : "+f"(d[0]), "+f"(d[1]), "+f"(d[2]), "+f"(d[3])
        : "r"(a[0]), "r"(a[1]), "r"(a[2]), "r"(a[3]), "r"(b0), "r"(b1));
}

// ---------------------------------------------------------------------------
// Fused fp32 -> bf16 conversion, 32B read / 16B write per thread.
// ---------------------------------------------------------------------------
__global__ __launch_bounds__(256)
void cvt_all_kernel(const float* __restrict__ nf, const float* __restrict__ wo,
                    const float* __restrict__ qf, const float* __restrict__ wq,
                    __nv_bfloat16* __restrict__ nodeB, __nv_bfloat16* __restrict__ wobjB,
                    __nv_bfloat16* __restrict__ qB, __nv_bfloat16* __restrict__ wqB)
{
    const int bid = blockIdx.x;
    const float* src; __nv_bfloat16* dst; int lb;
    if (bid < 4096)      { src = nf; dst = nodeB; lb = bid; }
    else if (bid < 4608) { src = wo; dst = wobjB; lb = bid - 4096; }
    else if (bid < 4640) { src = qf; dst = qB;    lb = bid - 4608; }
    else                 { src = wq; dst = wqB;   lb = bid - 4640; }
    const int i = lb * 256 + threadIdx.x;
    float4 v0 = ((const float4*)src)[i * 2];
    float4 v1 = ((const float4*)src)[i * 2 + 1];
    __nv_bfloat162 o0 = __floats2bfloat162_rn(v0.x, v0.y);
    __nv_bfloat162 o1 = __floats2bfloat162_rn(v0.z, v0.w);
    __nv_bfloat162 o2 = __floats2bfloat162_rn(v1.x, v1.y);
    __nv_bfloat162 o3 = __floats2bfloat162_rn(v1.z, v1.w);
    uint4 pack;
    pack.x = *(uint32_t*)&o0; pack.y = *(uint32_t*)&o1;
    pack.z = *(uint32_t*)&o2; pack.w = *(uint32_t*)&o3;
    ((uint4*)dst)[i] = pack;
}

// ---------------------------------------------------------------------------
// GEMM2: q_h[64,4096] = relu(q_feats @ W_q + b_q), fused norm partials.
// BM=64, BN=32, BK=64, 4 warps, 3-stage pipeline, grid = 128.
// ---------------------------------------------------------------------------
__global__ __launch_bounds__(128)
void gemm2_kernel(const __nv_bfloat16* __restrict__ A, const __nv_bfloat16* __restrict__ Bm,
                  const float* __restrict__ bias, float* __restrict__ C,
                  float* __restrict__ norm8)
{
    constexpr int BM = 64, BN = 32, BK = 64, S = 3;
    constexpr int AP = BK + 8, BP = BN + 8;
    constexpr int STA = BM * AP * 2, STB = BK * BP * 2;
    constexpr int ACH = BM * BK / 8, BCH = BK * BN / 8;
    constexpr int PT = (ACH + BCH) / 128;
    constexpr int NIT = QDIM / BK;
    constexpr int CP = BN + 4;

    extern __shared__ __align__(16) char smem[];
    const uint32_t sA = smem_u32(smem);
    const uint32_t sB = sA + S * STA;

    const int tid = threadIdx.x;
    const int wid = tid >> 5;
    const int wm = wid & 1, wn = wid >> 1;
    const int bN = blockIdx.x * BN;

    auto load_slab = [&](int slab) {
        const int s = slab % S, k0 = slab * BK;
#pragma unroll
        for (int t = 0; t < PT; t++) {
            int l = tid + t * 128;
            if (l < ACH) {
                int r = l >> 3, c = l & 7;
                cp_async16(sA + s * STA + (r * AP + c * 8) * 2,
                           A + (size_t)r * QDIM + k0 + c * 8);
            } else {
                int l2 = l - ACH;
                int r = l2 >> 2, c = l2 & 3;
                cp_async16(sB + s * STB + (r * BP + c * 8) * 2,
                           Bm + (size_t)(k0 + r) * HIDKS + bN + c * 8);
            }
        }
    };

    wmma::fragment<wmma::accumulator, 16, 16, 16, float> acc[2];
#pragma unroll
    for (int f = 0; f < 2; f++) wmma::fill_fragment(acc[f], 0.0f);

#pragma unroll
    for (int s = 0; s < S; s++) { load_slab(s); cp_commit(); }

    for (int i = 0; i < NIT; i++) {
        cp_wait<S - 2>();
        __syncthreads();
        if (i >= 1) {
            int j = i - 1 + S;
            if (j < NIT) load_slab(j);
            cp_commit();
        }
        const __nv_bfloat16* as = (const __nv_bfloat16*)(smem + (size_t)(i % S) * STA);
        const __nv_bfloat16* bs = (const __nv_bfloat16*)(smem + (size_t)S * STA + (size_t)(i % S) * STB);
#pragma unroll
        for (int kk = 0; kk < BK / 16; kk++) {
            wmma::fragment<wmma::matrix_a, 16, 16, 16, __nv_bfloat16, wmma::row_major> af[2];
            wmma::fragment<wmma::matrix_b, 16, 16, 16, __nv_bfloat16, wmma::row_major> bf;
#pragma unroll
            for (int f = 0; f < 2; f++)
                wmma::load_matrix_sync(af[f], as + (wm * 32 + f * 16) * AP + kk * 16, AP);
            wmma::load_matrix_sync(bf, bs + (kk * 16) * BP + wn * 16, BP);
#pragma unroll
            for (int f = 0; f < 2; f++)
                wmma::mma_sync(acc[f], af[f], bf, acc[f]);
        }
    }

    __syncthreads();
    float* Cs = (float*)smem;
    float* biasS = Cs + BM * CP;
#pragma unroll
    for (int f = 0; f < 2; f++)
        wmma::store_matrix_sync(Cs + (wm * 32 + f * 16) * CP + wn * 16,
                                acc[f], CP, wmma::mem_row_major);
    if (tid < BN) biasS[tid] = bias[bN + tid];
    __syncthreads();

#pragma unroll
    for (int t = 0; t < 4; t++) {
        int l = tid + t * 128;
        int r = l >> 3, c4 = (l & 7) * 4;
        float4 v = *(float4*)(Cs + r * CP + c4);
        v.x = fmaxf(v.x + biasS[c4 + 0], 0.0f);
        v.y = fmaxf(v.y + biasS[c4 + 1], 0.0f);
        v.z = fmaxf(v.z + biasS[c4 + 2], 0.0f);
        v.w = fmaxf(v.w + biasS[c4 + 3], 0.0f);
        *(float4*)(C + (size_t)r * HIDKS + bN + c4) = v;
    }
    // Norm partials, layout [b][k][ntile]
    if (tid < BM) {
        float a[KS];
#pragma unroll
        for (int k = 0; k < KS; k++) a[k] = 0.0f;
#pragma unroll
        for (int c = 0; c < BN; c++) {
            float v = fmaxf(Cs[tid * CP + c] + biasS[c], 0.0f);
            a[c & 7] += v * v;
        }
#pragma unroll
        for (int k = 0; k < KS; k++)
            norm8[(size_t)(tid * KS + k) * N2TILES + blockIdx.x] = a[k];
    }
}

// ---------------------------------------------------------------------------
// GEMM1: hand-rolled mma.sync.m16n8k16 + ldmatrix, register double-buffered.
// BM=128, BN=64, BK=64, 8 warps (256 thr), warp tile 32x32 (FM=2 m16, FN=4 n8).
// 3-stage cp.async pipeline; 83 KB smem -> 2 CTAs/SM. Epilogue contracts the
// C tile against q_h into P8 (node_h never hits global memory).
// ---------------------------------------------------------------------------
__global__ __launch_bounds__(256, 2)
void gemm1_kernel(const __nv_bfloat16* __restrict__ A, const __nv_bfloat16* __restrict__ Bm,
                  const float* __restrict__ bias, const float* __restrict__ qh,
                  float* __restrict__ P8)
{
    constexpr int BM = 128, BN = 64, BK = 64, S = 3;
    constexpr int AP = 72, BP = 72;                        // bf16 elems (pad 8)
    constexpr int STA = BM * AP * 2, STB = BK * BP * 2;    // 18432, 9216
    constexpr int ACH = BM * BK / 8, BCH = BK * BN / 8;    // 1024, 512
    constexpr int PT = (ACH + BCH) / 256;                  // 6
    constexpr int NIT = OBJDIM / BK;                       // 32
    constexpr int CP = BN + 4;                             // 68
    constexpr int ROWB = AP * 2;                           // 144 B row stride

    extern __shared__ __align__(16) char smem[];
    const uint32_t sA = smem_u32(smem);
    const uint32_t sB = sA + S * STA;

    const int tid  = threadIdx.x;
    const int wid  = tid >> 5;
    const int lane = tid & 31;
    const int wm = wid & 3, wn = wid >> 2;                 // 4 x 2 warps
    const int bM = blockIdx.y * BM;
    const int bN = blockIdx.x * BN;

    auto load_slab = [&](int slab) {
        const int s = slab % S, k0 = slab * BK;
#pragma unroll
        for (int t = 0; t < PT; t++) {
            int l = tid + t * 256;
            if (l < ACH) {
                int r = l >> 3, c = l & 7;
                cp_async16(sA + s * STA + r * ROWB + c * 16,
                           A + (size_t)(bM + r) * OBJDIM + k0 + c * 8);
            } else {
                int l2 = l - ACH;
                int r = l2 >> 3, c = l2 & 7;
                cp_async16(sB + s * STB + r * ROWB + c * 16,
                           Bm + (size_t)(k0 + r) * HID + bN + c * 8);
            }
        }
    };

    float acc[2][4][4];
#pragma unroll
    for (int f = 0; f < 2; f++)
#pragma unroll
        for (int j = 0; j < 4; j++)
#pragma unroll
            for (int e = 0; e < 4; e++) acc[f][j][e] = 0.0f;

    // lane-constant address parts
    // A tile (f, kk): rows m = wm*32 + f*16 + (lane&15), col-bytes kk*32 + (lane>>4)*16
    const uint32_t aLane = (uint32_t)((wm * 32 + (lane & 15)) * ROWB + (lane >> 4) * 16);
    // B tile (nh, kk): rows k = kk*16 + (lane&15), col-bytes wn*64 + nh*32 + (lane>>4)*16
    const uint32_t bLane = (uint32_t)((lane & 15) * ROWB + wn * 64 + (lane >> 4) * 16);

#pragma unroll
    for (int s = 0; s < S; s++) { load_slab(s); cp_commit(); }

    for (int i = 0; i < NIT; i++) {
        cp_wait<S - 2>();
        __syncthreads();
        if (i >= 1) {
            int j = i - 1 + S;
            if (j < NIT) load_slab(j);
            cp_commit();
        }
        const uint32_t aSt = sA + (i % S) * STA + aLane;
        const uint32_t bSt = sB + (i % S) * STB + bLane;

        uint32_t Ab[2][2][4];     // [buf][f][4]
        uint32_t Bb[2][2][4];     // [buf][nh][4]  (r0=b0 n0-7, r1=b1 n0-7, r2=b0 n8-15, r3=b1 n8-15)
        // kk = 0 into buf 0
        ldsm_x4(Ab[0][0][0], Ab[0][0][1], Ab[0][0][2], Ab[0][0][3], aSt);
        ldsm_x4(Ab[0][1][0], Ab[0][1][1], Ab[0][1][2], Ab[0][1][3], aSt + 16 * ROWB);
        ldsm_x4_t(Bb[0][0][0], Bb[0][0][1], Bb[0][0][2], Bb[0][0][3], bSt);
        ldsm_x4_t(Bb[0][1][0], Bb[0][1][1], Bb[0][1][2], Bb[0][1][3], bSt + 32);
#pragma unroll
        for (int kk = 0; kk < 4; kk++) {
            const int cur = kk & 1, nxt = cur ^ 1;
            if (kk < 3) {
                const uint32_t aN = aSt + (kk + 1) * 32;
                const uint32_t bN2 = bSt + (kk + 1) * 16 * ROWB;
                ldsm_x4(Ab[nxt][0][0], Ab[nxt][0][1], Ab[nxt][0][2], Ab[nxt][0][3], aN);
                ldsm_x4(Ab[nxt][1][0], Ab[nxt][1][1], Ab[nxt][1][2], Ab[nxt][1][3], aN + 16 * ROWB);
                ldsm_x4_t(Bb[nxt][0][0], Bb[nxt][0][1], Bb[nxt][0][2], Bb[nxt][0][3], bN2);
                ldsm_x4_t(Bb[nxt][1][0], Bb[nxt][1][1], Bb[nxt][1][2], Bb[nxt][1][3], bN2 + 32);
            }
#pragma unroll
            for (int f = 0; f < 2; f++) {
                mma_bf16(acc[f][0], Ab[cur][f], Bb[cur][0][0], Bb[cur][0][1]);
                mma_bf16(acc[f][1], Ab[cur][f], Bb[cur][0][2], Bb[cur][0][3]);
                mma_bf16(acc[f][2], Ab[cur][f], Bb[cur][1][0], Bb[cur][1][1]);
                mma_bf16(acc[f][3], Ab[cur][f], Bb[cur][1][2], Bb[cur][1][3]);
            }
        }
    }

    // Epilogue: acc -> Cs, then contract vs q_h into P8 (exclusive writes)
    __syncthreads();
    float* Cs    = (float*)smem;                 // 128 x 68 = 34816 B
    float* qs    = Cs + BM * CP;                 // 1024 floats
    float* biasS = qs + 1024;                    // 64 floats
#pragma unroll
    for (int f = 0; f < 2; f++)
#pragma unroll
        for (int j = 0; j < 4; j++) {
            const int row = wm * 32 + f * 16 + (lane >> 2);
            const int col = wn * 32 + j * 8 + (lane & 3) * 2;
            *(float2*)(Cs + row * CP + col)       = make_float2(acc[f][j][0], acc[f][j][1]);
            *(float2*)(Cs + (row + 8) * CP + col) = make_float2(acc[f][j][2], acc[f][j][3]);
        }
    {   // stage q_h segments for the two batches covered by this M-tile
        const int bB0 = bM >> 6;
        const int s = tid >> 7, i4 = (tid & 127) * 4;
        *(float4*)(qs + s * 512 + i4) =
            *(const float4*)(qh + (size_t)(bB0 + s) * HIDKS + bN * KS + i4);
        if (tid < BN) biasS[tid] = bias[bN + tid];
    }
    __syncthreads();

    // 2 threads per row, 32 cols each; combine via shfl
    const int r = tid >> 1;
    const int ch = (tid & 1) * 32;
    const float* qsp = qs + (r >> 6) * 512;
    float a[KS];
#pragma unroll
    for (int k = 0; k < KS; k++) a[k] = 0.0f;
#pragma unroll 8
    for (int cc = 0; cc < 32; cc++) {
        const int c = ch + cc;
        float v = fmaxf(Cs[r * CP + c] + biasS[c], 0.0f);
        float4 q0 = *(const float4*)(qsp + c * 8);
        float4 q1 = *(const float4*)(qsp + c * 8 + 4);
        a[0] += v * q0.x; a[1] += v * q0.y; a[2] += v * q0.z; a[3] += v * q0.w;
        a[4] += v * q1.x; a[5] += v * q1.y; a[6] += v * q1.z; a[7] += v * q1.w;
    }
#pragma unroll
    for (int k = 0; k < KS; k++)
        a[k] += __shfl_xor_sync(0xFFFFFFFFu, a[k], 1);
    if ((tid & 1) == 0) {
        float* dst = P8 + (size_t)blockIdx.x * (4096 * KS) + (size_t)(bM + r) * KS;
        *(float4*)dst       = make_float4(a[0], a[1], a[2], a[3]);
        *(float4*)(dst + 4) = make_float4(a[4], a[5], a[6], a[7]);
    }
}

// ---------------------------------------------------------------------------
// Fused finalize + gather: one block per batch (64 blocks, 256 threads).
// ---------------------------------------------------------------------------
__global__ __launch_bounds__(256)
void finalize_gather_kernel(const int* __restrict__ idxs, const float* __restrict__ P8,
                            const float* __restrict__ norm8, float* __restrict__ out)
{
    __shared__ float Ps[N_OBJ * KS];             // 512 floats
    __shared__ float normS[KS * 16];
    __shared__ float invS[KS];
    const int b   = blockIdx.x;
    const int tid = threadIdx.x;

    if (tid < 128) {
        // each thread one float4 of P: 8 partials at 32KB stride (MLP=8)
        const float4* src = (const float4*)P8;
        const int base = b * N_OBJ * 2;
        float4 s = make_float4(0.f, 0.f, 0.f, 0.f);
#pragma unroll
        for (int nt = 0; nt < 8; nt++) {
            float4 v = src[nt * 8192 + base + tid];
            s.x += v.x; s.y += v.y; s.z += v.z; s.w += v.w;
        }
        ((float4*)Ps)[tid] = s;
    } else {
        // norm8 layout [b][k][nt]: 16 threads per k, 8 contiguous floats each
        const int t = tid - 128;
        const int k = t >> 4, j = t & 15;
        const float4* src = (const float4*)(norm8 + (size_t)(b * KS + k) * N2TILES + j * 8);
        float4 v0 = src[0], v1 = src[1];
        normS[k * 16 + j] = v0.x + v0.y + v0.z + v0.w + v1.x + v1.y + v1.z + v1.w;
    }
    __syncthreads();
    if (tid < KS) {
        float s = 0.f;
#pragma unroll
        for (int p = 0; p < 16; p++) s += normS[tid * 16 + p];
        invS[tid] = rsqrtf(s);
    }
    __syncthreads();

    const float4 i0 = *(const float4*)invS;
    const float4 i1 = *(const float4*)(invS + 4);
#pragma unroll
    for (int e = 0; e < 2; e++) {
        const int m = b * 512 + tid + e * 256;
        const int idx = __ldg(idxs + m);
        const int rem = idx & 4095;
        const int src = rem >> 6, dst = rem & 63;
        const float4* ps = (const float4*)(Ps + src * KS);
        const float4* pd = (const float4*)(Ps + dst * KS);
        float4 s0 = ps[0], s1 = ps[1], d0 = pd[0], d1 = pd[1];
        float4 o0 = make_float4((s0.x + d0.x) * i0.x, (s0.y + d0.y) * i0.y,
                                (s0.z + d0.z) * i0.z, (s0.w + d0.w) * i0.w);
        float4 o1 = make_float4((s1.x + d1.x) * i1.x, (s1.y + d1.y) * i1.y,
                                (s1.z + d1.z) * i1.z, (s1.w + d1.w) * i1.w);
        ((float4*)out)[(size_t)m * 2]     = o0;
        ((float4*)out)[(size_t)m * 2 + 1] = o1;
    }
}

// ---------------------------------------------------------------------------
extern "C" void kernel_launch(void* const* d_in, const int* in_sizes, int n_in,
                              void* d_out, int out_size)
{
    const float* node_feats = (const float*)d_in[0];
    const float* q_feats    = (const float*)d_in[1];
    const int*   indexes    = (const int*)d_in[2];
    const float* W_obj      = (const float*)d_in[3];
    const float* b_obj      = (const float*)d_in[4];
    const float* W_q        = (const float*)d_in[5];
    const float* b_q        = (const float*)d_in[6];
    float* out = (float*)d_out;

    __nv_bfloat16 *nodeB, *wobjB, *qB, *wqB;
    float *qh, *P8, *norm8;
    cudaGetSymbolAddress((void**)&nodeB, g_nodeB);
    cudaGetSymbolAddress((void**)&wobjB, g_WobjB);
    cudaGetSymbolAddress((void**)&qB,    g_qB);
    cudaGetSymbolAddress((void**)&wqB,   g_WqB);
    cudaGetSymbolAddress((void**)&qh,    g_q_h);
    cudaGetSymbolAddress((void**)&P8,    g_P8);
    cudaGetSymbolAddress((void**)&norm8, g_norm8);

    // 1) all fp32 -> bf16 conversions, one launch
    cvt_all_kernel<<<6688, 256>>>(node_feats, W_obj, q_feats, W_q,
                                  nodeB, wobjB, qB, wqB);

    // 2) GEMM2 + norm partials (must precede GEMM1: epilogue consumes q_h)
    {
        constexpr int SM = 3 * (64 * 72 * 2 + 64 * 40 * 2);      // 43008
        cudaFuncSetAttribute(gemm2_kernel, cudaFuncAttributeMaxDynamicSharedMemorySize, SM);
        gemm2_kernel<<<N2TILES, 128, SM>>>(qB, wqB, b_q, qh, norm8);
    }
    // 3) GEMM1 (hand-rolled mma.sync) fused with P contraction
    {
        constexpr int SM = 3 * (128 * 72 * 2 + 64 * 72 * 2);     // 82944
        cudaFuncSetAttribute(gemm1_kernel, cudaFuncAttributeMaxDynamicSharedMemorySize, SM);
        gemm1_kernel<<<dim3(HID / 64, 4096 / 128), 256, SM>>>(nodeB, wobjB, b_obj, qh, P8);
    }
    // 4) fused finalize + edge gather (one block per batch)
    finalize_gather_kernel<<<B_IMG, 256>>>(indexes, P8, norm8, out);
}